// round 2
// baseline (speedup 1.0000x reference)
#include <cuda_runtime.h>
#include <cuda_bf16.h>
#include <cstdint>

// Problem constants (from reference setup_inputs): N=100000, IN=512, OUT=256, E=3.2M
#define IN_DIM  512
#define OUT_DIM 256
#define MAX_N   100000

// Scratch: support = tanh(x @ weight), [N, 256] fp32 (102.4 MB).
// Referenced directly from device code -- no host-side symbol query needed.
__device__ float g_support[(size_t)MAX_N * OUT_DIM];

// ---------------------------------------------------------------------------
// Kernel 1: tiled fp32 GEMM [N,512] @ [512,256] with optional tanh epilogue
// BM=64, BN=64, BK=16, 256 threads, 4x4 per-thread microtile
// ---------------------------------------------------------------------------
#define BM 64
#define BN 64
#define BK 16
#define TM 4
#define TN 4

__global__ __launch_bounds__(256)
void gemm_tanh_kernel(const float* __restrict__ x,
                      const float* __restrict__ w,
                      const int*   __restrict__ active,
                      int N)
{
    __shared__ float As[BK][BM];      // A^T tile: As[k][m]
    __shared__ float Bs[BK][BN + 4];  // pad to soften bank conflicts

    const int tid = threadIdx.x;
    const int block_row = blockIdx.y * BM;
    const int block_col = blockIdx.x * BN;

    const int tx = tid & 15;   // output-col group (0..15)
    const int ty = tid >> 4;   // output-row group (0..15)

    float acc[TM][TN];
    #pragma unroll
    for (int i = 0; i < TM; i++)
        #pragma unroll
        for (int j = 0; j < TN; j++)
            acc[i][j] = 0.0f;

    // load indices
    const int a_row  = tid >> 2;        // 0..63
    const int a_col  = (tid & 3) * 4;   // 0,4,8,12
    const int b_row  = tid >> 4;        // 0..15
    const int b_col  = (tid & 15) * 4;  // 0..60

    const int grow_a = block_row + a_row;
    const bool a_ok  = (grow_a < N);
    const float* a_ptr = x + (size_t)(a_ok ? grow_a : 0) * IN_DIM;

    for (int k0 = 0; k0 < IN_DIM; k0 += BK) {
        float4 av = a_ok ? *(const float4*)(a_ptr + k0 + a_col)
                         : make_float4(0.f, 0.f, 0.f, 0.f);
        As[a_col + 0][a_row] = av.x;
        As[a_col + 1][a_row] = av.y;
        As[a_col + 2][a_row] = av.z;
        As[a_col + 3][a_row] = av.w;

        float4 bv = *(const float4*)(w + (size_t)(k0 + b_row) * OUT_DIM + block_col + b_col);
        *(float4*)&Bs[b_row][b_col] = bv;

        __syncthreads();

        #pragma unroll
        for (int k = 0; k < BK; k++) {
            float a[TM], b[TN];
            #pragma unroll
            for (int i = 0; i < TM; i++) a[i] = As[k][ty * TM + i];
            #pragma unroll
            for (int j = 0; j < TN; j++) b[j] = Bs[k][tx * TN + j];
            #pragma unroll
            for (int i = 0; i < TM; i++)
                #pragma unroll
                for (int j = 0; j < TN; j++)
                    acc[i][j] = fmaf(a[i], b[j], acc[i][j]);
        }
        __syncthreads();
    }

    const bool act = (*active) != 0;
    #pragma unroll
    for (int i = 0; i < TM; i++) {
        int grow = block_row + ty * TM + i;
        if (grow >= N) continue;
        float v0 = acc[i][0], v1 = acc[i][1], v2 = acc[i][2], v3 = acc[i][3];
        if (act) { v0 = tanhf(v0); v1 = tanhf(v1); v2 = tanhf(v2); v3 = tanhf(v3); }
        *(float4*)(g_support + (size_t)grow * OUT_DIM + block_col + tx * TN)
            = make_float4(v0, v1, v2, v3);
    }
}

// ---------------------------------------------------------------------------
// Kernel 2: zero the output (d_out is poisoned by the harness)
// ---------------------------------------------------------------------------
__global__ void zero_kernel(float4* __restrict__ out, int n4)
{
    int idx = blockIdx.x * blockDim.x + threadIdx.x;
    int stride = gridDim.x * blockDim.x;
    float4 z = make_float4(0.f, 0.f, 0.f, 0.f);
    for (int i = idx; i < n4; i += stride)
        out[i] = z;
}

// ---------------------------------------------------------------------------
// Kernel 3: scatter-add. One warp per edge: gather support[col]*val (1 KB,
// 32 lanes x 2 float4) and reduce into out[row] via red.global.add.v4.f32
// (no-return atomics: no scoreboard dependency, 4x fewer red ops).
// ---------------------------------------------------------------------------
__device__ __forceinline__ void red_add_v4(float* addr, float4 v)
{
    asm volatile("red.global.add.v4.f32 [%0], {%1, %2, %3, %4};"
                 :: "l"(addr), "f"(v.x), "f"(v.y), "f"(v.z), "f"(v.w)
                 : "memory");
}

__global__ __launch_bounds__(256)
void scatter_kernel(const int*   __restrict__ rows,
                    const int*   __restrict__ cols,
                    const float* __restrict__ vals,
                    float*       __restrict__ out,
                    int E)
{
    int warp = (blockIdx.x * blockDim.x + threadIdx.x) >> 5;
    int lane = threadIdx.x & 31;
    if (warp >= E) return;

    int   r = rows[warp];
    int   c = cols[warp];
    float v = vals[warp];

    const float4* src = (const float4*)(g_support + (size_t)c * OUT_DIM);
    float*        dst = out + (size_t)r * OUT_DIM;

    // 256 floats = 64 float4; 32 lanes x 2 iterations
    #pragma unroll
    for (int i = 0; i < 2; i++) {
        int idx = lane + i * 32;
        float4 s = src[idx];
        s.x *= v; s.y *= v; s.z *= v; s.w *= v;
        red_add_v4(dst + idx * 4, s);
    }
}

// ---------------------------------------------------------------------------
// Launch
// Inputs (metadata order): x[N,512] f32, weight[512,256] f32,
//   edge_rows[E] i32, edge_cols[E] i32, edge_vals[E] f32, active i32
// Output: [N,256] f32
// ---------------------------------------------------------------------------
extern "C" void kernel_launch(void* const* d_in, const int* in_sizes, int n_in,
                              void* d_out, int out_size)
{
    const float* x      = (const float*)d_in[0];
    const float* w      = (const float*)d_in[1];
    const int*   erows  = (const int*)d_in[2];
    const int*   ecols  = (const int*)d_in[3];
    const float* evals  = (const float*)d_in[4];
    const int*   active = (const int*)d_in[5];
    float*       out    = (float*)d_out;

    const int N = in_sizes[0] / IN_DIM;
    const int E = in_sizes[2];

    // 1) g_support = tanh?(x @ w)
    dim3 ggrid(OUT_DIM / BN, (N + BM - 1) / BM);
    gemm_tanh_kernel<<<ggrid, 256>>>(x, w, active, N);

    // 2) out = 0
    int n4 = out_size / 4;
    zero_kernel<<<1024, 256>>>((float4*)out, n4);

    // 3) out[r] += v * support[c] over all edges (one warp per edge)
    long long total_threads = (long long)E * 32;
    int blocks = (int)((total_threads + 255) / 256);
    scatter_kernel<<<blocks, 256>>>(erows, ecols, evals, out, E);
}

// round 3
// speedup vs baseline: 1.6608x; 1.6608x over previous
#include <cuda_runtime.h>
#include <cuda_bf16.h>
#include <cstdint>

// Problem constants: N=100000, IN=512, OUT=256, E=3.2M
#define IN_DIM  512
#define OUT_DIM 256
#define MAX_N   100000
#define MAX_E   3200000

// Scratch (device globals -- no runtime allocation allowed)
__device__ float g_support[(size_t)MAX_N * OUT_DIM];   // 102.4 MB
__device__ int   g_count[MAX_N];                       // per-row edge count
__device__ int   g_offset[MAX_N + 1];                  // CSR row offsets (exclusive scan)
__device__ int   g_cursor[MAX_N];                      // running cursors for reorder
__device__ int2  g_edges[MAX_E];                       // row-sorted (col, val-bits), 25.6 MB

// ---------------------------------------------------------------------------
// Kernel 1: 128x128x16 fp32 GEMM, 8x8 microtile, optional tanh epilogue
// ---------------------------------------------------------------------------
#define BM 128
#define BN 128
#define BK 16
#define PAD 4

__global__ __launch_bounds__(256)
void gemm_tanh_kernel(const float* __restrict__ x,
                      const float* __restrict__ w,
                      const int*   __restrict__ active,
                      int N)
{
    __shared__ float As[BK][BM + PAD];   // A^T: As[k][m]
    __shared__ float Bs[BK][BN + PAD];

    const int tid = threadIdx.x;
    const int block_row = blockIdx.y * BM;
    const int block_col = blockIdx.x * BN;

    const int tx = tid & 15;   // col group (0..15) -> 8 cols each
    const int ty = tid >> 4;   // row group (0..15) -> 8 rows each

    float acc[8][8];
    #pragma unroll
    for (int i = 0; i < 8; i++)
        #pragma unroll
        for (int j = 0; j < 8; j++)
            acc[i][j] = 0.0f;

    // A loads: 128 rows x 16 cols = 512 float4, 2 per thread (rows r and r+64)
    const int a_row0 = tid >> 2;            // 0..63
    const int a_col  = (tid & 3) * 4;       // 0,4,8,12
    // B loads: 16 rows x 128 cols = 512 float4, 2 per thread (rows r and r+8)
    const int b_row0 = tid >> 5;            // 0..7
    const int b_col  = (tid & 31) * 4;      // 0..124

    const int gr0 = block_row + a_row0;
    const int gr1 = block_row + a_row0 + 64;
    const bool ok0 = (gr0 < N);
    const bool ok1 = (gr1 < N);
    const float* a_ptr0 = x + (size_t)(ok0 ? gr0 : 0) * IN_DIM;
    const float* a_ptr1 = x + (size_t)(ok1 ? gr1 : 0) * IN_DIM;

    for (int k0 = 0; k0 < IN_DIM; k0 += BK) {
        float4 av0 = ok0 ? *(const float4*)(a_ptr0 + k0 + a_col) : make_float4(0,0,0,0);
        float4 av1 = ok1 ? *(const float4*)(a_ptr1 + k0 + a_col) : make_float4(0,0,0,0);
        As[a_col + 0][a_row0]      = av0.x;
        As[a_col + 1][a_row0]      = av0.y;
        As[a_col + 2][a_row0]      = av0.z;
        As[a_col + 3][a_row0]      = av0.w;
        As[a_col + 0][a_row0 + 64] = av1.x;
        As[a_col + 1][a_row0 + 64] = av1.y;
        As[a_col + 2][a_row0 + 64] = av1.z;
        As[a_col + 3][a_row0 + 64] = av1.w;

        float4 bv0 = *(const float4*)(w + (size_t)(k0 + b_row0) * OUT_DIM + block_col + b_col);
        float4 bv1 = *(const float4*)(w + (size_t)(k0 + b_row0 + 8) * OUT_DIM + block_col + b_col);
        *(float4*)&Bs[b_row0][b_col]     = bv0;
        *(float4*)&Bs[b_row0 + 8][b_col] = bv1;

        __syncthreads();

        #pragma unroll
        for (int k = 0; k < BK; k++) {
            float a[8], b[8];
            *(float4*)&a[0] = *(const float4*)&As[k][ty * 8];
            *(float4*)&a[4] = *(const float4*)&As[k][ty * 8 + 4];
            *(float4*)&b[0] = *(const float4*)&Bs[k][tx * 8];
            *(float4*)&b[4] = *(const float4*)&Bs[k][tx * 8 + 4];
            #pragma unroll
            for (int i = 0; i < 8; i++)
                #pragma unroll
                for (int j = 0; j < 8; j++)
                    acc[i][j] = fmaf(a[i], b[j], acc[i][j]);
        }
        __syncthreads();
    }

    const bool act = (*active) != 0;
    #pragma unroll
    for (int i = 0; i < 8; i++) {
        int grow = block_row + ty * 8 + i;
        if (grow >= N) continue;
        float* dst = g_support + (size_t)grow * OUT_DIM + block_col + tx * 8;
        float v[8];
        #pragma unroll
        for (int j = 0; j < 8; j++) v[j] = act ? tanhf(acc[i][j]) : acc[i][j];
        *(float4*)(dst)     = make_float4(v[0], v[1], v[2], v[3]);
        *(float4*)(dst + 4) = make_float4(v[4], v[5], v[6], v[7]);
    }
}

// ---------------------------------------------------------------------------
// CSR build: zero counters -> histogram -> exclusive scan -> reorder
// ---------------------------------------------------------------------------
__global__ void zero_count_kernel(int N)
{
    int i = blockIdx.x * blockDim.x + threadIdx.x;
    if (i < N) g_count[i] = 0;
}

__global__ void hist_kernel(const int* __restrict__ rows, int E)
{
    int i = blockIdx.x * blockDim.x + threadIdx.x;
    if (i < E) atomicAdd(&g_count[rows[i]], 1);
}

// Single-block exclusive scan over g_count -> g_offset (N+1) and g_cursor.
__global__ __launch_bounds__(1024)
void scan_kernel(int N)
{
    __shared__ int carry;
    __shared__ int warp_sums[32];
    const int tid  = threadIdx.x;
    const int lane = tid & 31;
    const int wid  = tid >> 5;

    if (tid == 0) carry = 0;
    __syncthreads();

    for (int base = 0; base < N; base += 1024) {
        int i = base + tid;
        int v = (i < N) ? g_count[i] : 0;

        // inclusive scan within warp
        int s = v;
        #pragma unroll
        for (int off = 1; off < 32; off <<= 1) {
            int t = __shfl_up_sync(0xFFFFFFFFu, s, off);
            if (lane >= off) s += t;
        }
        if (lane == 31) warp_sums[wid] = s;
        __syncthreads();

        if (wid == 0) {
            int ws = warp_sums[lane];
            #pragma unroll
            for (int off = 1; off < 32; off <<= 1) {
                int t = __shfl_up_sync(0xFFFFFFFFu, ws, off);
                if (lane >= off) ws += t;
            }
            warp_sums[lane] = ws;   // inclusive across warps
        }
        __syncthreads();

        int excl = carry + (wid > 0 ? warp_sums[wid - 1] : 0) + (s - v);
        if (i < N) {
            g_offset[i] = excl;
            g_cursor[i] = excl;
        }
        __syncthreads();
        if (tid == 0) carry += warp_sums[31];
        __syncthreads();
    }
    if (tid == 0) g_offset[N] = carry;
}

__global__ void reorder_kernel(const int* __restrict__ rows,
                               const int* __restrict__ cols,
                               const float* __restrict__ vals,
                               int E)
{
    int i = blockIdx.x * blockDim.x + threadIdx.x;
    if (i >= E) return;
    int r = rows[i];
    int pos = atomicAdd(&g_cursor[r], 1);
    g_edges[pos] = make_int2(cols[i], __float_as_int(vals[i]));
}

// ---------------------------------------------------------------------------
// Gather SpMM: one warp per output row, no atomics.
// Each lane owns 8 output floats (2 float4: cols lane*4 and 128+lane*4).
// ---------------------------------------------------------------------------
__global__ __launch_bounds__(256)
void gather_kernel(float* __restrict__ out, int N)
{
    int warp = (blockIdx.x * blockDim.x + threadIdx.x) >> 5;
    int lane = threadIdx.x & 31;
    if (warp >= N) return;

    int beg = g_offset[warp];
    int end = g_offset[warp + 1];

    float4 acc0 = make_float4(0, 0, 0, 0);
    float4 acc1 = make_float4(0, 0, 0, 0);

    for (int e = beg; e < end; e++) {
        int2 ed = g_edges[e];                // broadcast load (same addr all lanes)
        int   c = ed.x;
        float v = __int_as_float(ed.y);
        const float4* src = (const float4*)(g_support + (size_t)c * OUT_DIM);
        float4 s0 = src[lane];
        float4 s1 = src[lane + 32];
        acc0.x = fmaf(v, s0.x, acc0.x);
        acc0.y = fmaf(v, s0.y, acc0.y);
        acc0.z = fmaf(v, s0.z, acc0.z);
        acc0.w = fmaf(v, s0.w, acc0.w);
        acc1.x = fmaf(v, s1.x, acc1.x);
        acc1.y = fmaf(v, s1.y, acc1.y);
        acc1.z = fmaf(v, s1.z, acc1.z);
        acc1.w = fmaf(v, s1.w, acc1.w);
    }

    float4* dst = (float4*)(out + (size_t)warp * OUT_DIM);
    dst[lane]      = acc0;
    dst[lane + 32] = acc1;
}

// ---------------------------------------------------------------------------
// Launch
// Inputs: x[N,512] f32, weight[512,256] f32, edge_rows[E] i32,
//         edge_cols[E] i32, edge_vals[E] f32, active i32
// Output: [N,256] f32
// ---------------------------------------------------------------------------
extern "C" void kernel_launch(void* const* d_in, const int* in_sizes, int n_in,
                              void* d_out, int out_size)
{
    const float* x      = (const float*)d_in[0];
    const float* w      = (const float*)d_in[1];
    const int*   erows  = (const int*)d_in[2];
    const int*   ecols  = (const int*)d_in[3];
    const float* evals  = (const float*)d_in[4];
    const int*   active = (const int*)d_in[5];
    float*       out    = (float*)d_out;

    const int N = in_sizes[0] / IN_DIM;
    const int E = in_sizes[2];

    // CSR build (independent of GEMM; same stream, serialized)
    zero_count_kernel<<<(N + 255) / 256, 256>>>(N);
    hist_kernel<<<(E + 255) / 256, 256>>>(erows, E);
    scan_kernel<<<1, 1024>>>(N);
    reorder_kernel<<<(E + 255) / 256, 256>>>(erows, ecols, evals, E);

    // GEMM: g_support = tanh?(x @ w)
    dim3 ggrid(OUT_DIM / BN, (N + BM - 1) / BM);
    gemm_tanh_kernel<<<ggrid, 256>>>(x, w, active, N);

    // Gather SpMM: out[r] = sum_{e in row r} v_e * support[c_e]
    int gblocks = (N * 32 + 255) / 256;
    gather_kernel<<<gblocks, 256>>>(out, N);
}

// round 4
// speedup vs baseline: 1.8615x; 1.1208x over previous
#include <cuda_runtime.h>
#include <cuda_fp16.h>
#include <cstdint>

// Problem constants: N=100000, IN=512, OUT=256, E=3.2M
#define IN_DIM  512
#define OUT_DIM 256
#define MAX_N   100000
#define MAX_E   3200000

// Scratch (device globals -- no runtime allocation allowed)
__device__ __half g_support[(size_t)MAX_N * OUT_DIM];  // 51.2 MB, fp16 tanh output
__device__ int    g_count[MAX_N];
__device__ int    g_offset[MAX_N + 1];
__device__ int    g_cursor[MAX_N];
__device__ int2   g_edges[MAX_E];                      // row-sorted (col, val-bits)

// ---------------------------------------------------------------------------
// Kernel 1: 128x128x16 fp32 GEMM, 8x8 microtile, tanh epilogue -> fp16 store
// ---------------------------------------------------------------------------
#define BM 128
#define BN 128
#define BK 16
#define PAD 4

__global__ __launch_bounds__(256)
void gemm_tanh_kernel(const float* __restrict__ x,
                      const float* __restrict__ w,
                      const int*   __restrict__ active,
                      int N)
{
    __shared__ float As[BK][BM + PAD];   // A^T: As[k][m]
    __shared__ float Bs[BK][BN + PAD];

    const int tid = threadIdx.x;
    const int block_row = blockIdx.y * BM;
    const int block_col = blockIdx.x * BN;

    const int tx = tid & 15;   // col group -> 8 cols each
    const int ty = tid >> 4;   // row group -> 8 rows each

    float acc[8][8];
    #pragma unroll
    for (int i = 0; i < 8; i++)
        #pragma unroll
        for (int j = 0; j < 8; j++)
            acc[i][j] = 0.0f;

    const int a_row0 = tid >> 2;
    const int a_col  = (tid & 3) * 4;
    const int b_row0 = tid >> 5;
    const int b_col  = (tid & 31) * 4;

    const int gr0 = block_row + a_row0;
    const int gr1 = block_row + a_row0 + 64;
    const bool ok0 = (gr0 < N);
    const bool ok1 = (gr1 < N);
    const float* a_ptr0 = x + (size_t)(ok0 ? gr0 : 0) * IN_DIM;
    const float* a_ptr1 = x + (size_t)(ok1 ? gr1 : 0) * IN_DIM;

    for (int k0 = 0; k0 < IN_DIM; k0 += BK) {
        float4 av0 = ok0 ? *(const float4*)(a_ptr0 + k0 + a_col) : make_float4(0,0,0,0);
        float4 av1 = ok1 ? *(const float4*)(a_ptr1 + k0 + a_col) : make_float4(0,0,0,0);
        As[a_col + 0][a_row0]      = av0.x;
        As[a_col + 1][a_row0]      = av0.y;
        As[a_col + 2][a_row0]      = av0.z;
        As[a_col + 3][a_row0]      = av0.w;
        As[a_col + 0][a_row0 + 64] = av1.x;
        As[a_col + 1][a_row0 + 64] = av1.y;
        As[a_col + 2][a_row0 + 64] = av1.z;
        As[a_col + 3][a_row0 + 64] = av1.w;

        float4 bv0 = *(const float4*)(w + (size_t)(k0 + b_row0) * OUT_DIM + block_col + b_col);
        float4 bv1 = *(const float4*)(w + (size_t)(k0 + b_row0 + 8) * OUT_DIM + block_col + b_col);
        *(float4*)&Bs[b_row0][b_col]     = bv0;
        *(float4*)&Bs[b_row0 + 8][b_col] = bv1;

        __syncthreads();

        #pragma unroll
        for (int k = 0; k < BK; k++) {
            float a[8], b[8];
            *(float4*)&a[0] = *(const float4*)&As[k][ty * 8];
            *(float4*)&a[4] = *(const float4*)&As[k][ty * 8 + 4];
            *(float4*)&b[0] = *(const float4*)&Bs[k][tx * 8];
            *(float4*)&b[4] = *(const float4*)&Bs[k][tx * 8 + 4];
            #pragma unroll
            for (int i = 0; i < 8; i++)
                #pragma unroll
                for (int j = 0; j < 8; j++)
                    acc[i][j] = fmaf(a[i], b[j], acc[i][j]);
        }
        __syncthreads();
    }

    const bool act = (*active) != 0;
    #pragma unroll
    for (int i = 0; i < 8; i++) {
        int grow = block_row + ty * 8 + i;
        if (grow >= N) continue;
        float v[8];
        #pragma unroll
        for (int j = 0; j < 8; j++) v[j] = act ? tanhf(acc[i][j]) : acc[i][j];
        // pack 8 floats -> 8 halves (16 B) -> one uint4 store
        __half2 h0 = __float22half2_rn(make_float2(v[0], v[1]));
        __half2 h1 = __float22half2_rn(make_float2(v[2], v[3]));
        __half2 h2 = __float22half2_rn(make_float2(v[4], v[5]));
        __half2 h3 = __float22half2_rn(make_float2(v[6], v[7]));
        uint4 pack;
        pack.x = *(unsigned*)&h0;
        pack.y = *(unsigned*)&h1;
        pack.z = *(unsigned*)&h2;
        pack.w = *(unsigned*)&h3;
        *(uint4*)(g_support + (size_t)grow * OUT_DIM + block_col + tx * 8) = pack;
    }
}

// ---------------------------------------------------------------------------
// CSR build
// ---------------------------------------------------------------------------
__global__ void zero_count_kernel(int N)
{
    int i = blockIdx.x * blockDim.x + threadIdx.x;
    if (i < N) g_count[i] = 0;
}

__global__ void hist_kernel(const int* __restrict__ rows, int E)
{
    int i = blockIdx.x * blockDim.x + threadIdx.x;
    int base = i * 4;
    if (base + 3 < E) {
        int4 r = *(const int4*)(rows + base);
        atomicAdd(&g_count[r.x], 1);
        atomicAdd(&g_count[r.y], 1);
        atomicAdd(&g_count[r.z], 1);
        atomicAdd(&g_count[r.w], 1);
    } else {
        for (int j = base; j < E; j++) atomicAdd(&g_count[rows[j]], 1);
    }
}

__global__ __launch_bounds__(1024)
void scan_kernel(int N)
{
    __shared__ int carry;
    __shared__ int warp_sums[32];
    const int tid  = threadIdx.x;
    const int lane = tid & 31;
    const int wid  = tid >> 5;

    if (tid == 0) carry = 0;
    __syncthreads();

    for (int base = 0; base < N; base += 1024) {
        int i = base + tid;
        int v = (i < N) ? g_count[i] : 0;

        int s = v;
        #pragma unroll
        for (int off = 1; off < 32; off <<= 1) {
            int t = __shfl_up_sync(0xFFFFFFFFu, s, off);
            if (lane >= off) s += t;
        }
        if (lane == 31) warp_sums[wid] = s;
        __syncthreads();

        if (wid == 0) {
            int ws = warp_sums[lane];
            #pragma unroll
            for (int off = 1; off < 32; off <<= 1) {
                int t = __shfl_up_sync(0xFFFFFFFFu, ws, off);
                if (lane >= off) ws += t;
            }
            warp_sums[lane] = ws;
        }
        __syncthreads();

        int excl = carry + (wid > 0 ? warp_sums[wid - 1] : 0) + (s - v);
        if (i < N) {
            g_offset[i] = excl;
            g_cursor[i] = excl;
        }
        __syncthreads();
        if (tid == 0) carry += warp_sums[31];
        __syncthreads();
    }
    if (tid == 0) g_offset[N] = carry;
}

__global__ void reorder_kernel(const int* __restrict__ rows,
                               const int* __restrict__ cols,
                               const float* __restrict__ vals,
                               int E)
{
    int i = blockIdx.x * blockDim.x + threadIdx.x;
    if (i >= E) return;
    int r = rows[i];
    int pos = atomicAdd(&g_cursor[r], 1);
    g_edges[pos] = make_int2(cols[i], __float_as_int(vals[i]));
}

// ---------------------------------------------------------------------------
// Gather SpMM: one warp per output row, fp16 support, fp32 accumulation.
// Each lane owns 8 output cols [8*lane, 8*lane+8): one uint4 (8 halves) per
// edge, warp covers the full 512 B support row contiguously.
// ---------------------------------------------------------------------------
__device__ __forceinline__ void fma8_h(const uint4 p, float v, float* acc)
{
    float2 f0 = __half22float2(*(const __half2*)&p.x);
    float2 f1 = __half22float2(*(const __half2*)&p.y);
    float2 f2 = __half22float2(*(const __half2*)&p.z);
    float2 f3 = __half22float2(*(const __half2*)&p.w);
    acc[0] = fmaf(v, f0.x, acc[0]);
    acc[1] = fmaf(v, f0.y, acc[1]);
    acc[2] = fmaf(v, f1.x, acc[2]);
    acc[3] = fmaf(v, f1.y, acc[3]);
    acc[4] = fmaf(v, f2.x, acc[4]);
    acc[5] = fmaf(v, f2.y, acc[5]);
    acc[6] = fmaf(v, f3.x, acc[6]);
    acc[7] = fmaf(v, f3.y, acc[7]);
}

__global__ __launch_bounds__(256)
void gather_kernel(float* __restrict__ out, int N)
{
    int warp = (blockIdx.x * blockDim.x + threadIdx.x) >> 5;
    int lane = threadIdx.x & 31;
    if (warp >= N) return;

    int beg = g_offset[warp];
    int end = g_offset[warp + 1];

    float acc[8];
    #pragma unroll
    for (int j = 0; j < 8; j++) acc[j] = 0.0f;

    int e = beg;
    // unroll x2: issue both edges' loads before consuming
    for (; e + 1 < end; e += 2) {
        int2 ed0 = g_edges[e];
        int2 ed1 = g_edges[e + 1];
        const uint4* s0 = (const uint4*)(g_support + (size_t)ed0.x * OUT_DIM);
        const uint4* s1 = (const uint4*)(g_support + (size_t)ed1.x * OUT_DIM);
        uint4 p0 = s0[lane];
        uint4 p1 = s1[lane];
        fma8_h(p0, __int_as_float(ed0.y), acc);
        fma8_h(p1, __int_as_float(ed1.y), acc);
    }
    if (e < end) {
        int2 ed = g_edges[e];
        const uint4* s = (const uint4*)(g_support + (size_t)ed.x * OUT_DIM);
        uint4 p = s[lane];
        fma8_h(p, __int_as_float(ed.y), acc);
    }

    float* dst = out + (size_t)warp * OUT_DIM + lane * 8;
    *(float4*)(dst)     = make_float4(acc[0], acc[1], acc[2], acc[3]);
    *(float4*)(dst + 4) = make_float4(acc[4], acc[5], acc[6], acc[7]);
}

// ---------------------------------------------------------------------------
// Launch
// ---------------------------------------------------------------------------
extern "C" void kernel_launch(void* const* d_in, const int* in_sizes, int n_in,
                              void* d_out, int out_size)
{
    const float* x      = (const float*)d_in[0];
    const float* w      = (const float*)d_in[1];
    const int*   erows  = (const int*)d_in[2];
    const int*   ecols  = (const int*)d_in[3];
    const float* evals  = (const float*)d_in[4];
    const int*   active = (const int*)d_in[5];
    float*       out    = (float*)d_out;

    const int N = in_sizes[0] / IN_DIM;
    const int E = in_sizes[2];

    // CSR build
    zero_count_kernel<<<(N + 255) / 256, 256>>>(N);
    hist_kernel<<<((E + 3) / 4 + 255) / 256, 256>>>(erows, E);
    scan_kernel<<<1, 1024>>>(N);
    reorder_kernel<<<(E + 255) / 256, 256>>>(erows, ecols, evals, E);

    // GEMM: g_support = fp16(tanh?(x @ w))
    dim3 ggrid(OUT_DIM / BN, (N + BM - 1) / BM);
    gemm_tanh_kernel<<<ggrid, 256>>>(x, w, active, N);

    // Gather SpMM
    int gblocks = (N * 32 + 255) / 256;
    gather_kernel<<<gblocks, 256>>>(out, N);
}

// round 7
// speedup vs baseline: 3.8377x; 2.0616x over previous
#include <cuda_runtime.h>
#include <cuda_fp16.h>
#include <cstdint>

// Problem constants: N=100000, IN=512, OUT=256, E=3.2M
#define IN_DIM  512
#define OUT_DIM 256
#define MAX_N   100000
#define MAX_E   3200000

// Scratch (device globals -- no runtime allocation allowed)
__device__ __half g_support[(size_t)MAX_N * OUT_DIM];  // 51.2 MB fp16
__device__ __half g_wh[(size_t)OUT_DIM * IN_DIM];      // w^T [256][512] fp16, K-major
__device__ int    g_count[MAX_N];
__device__ int    g_offset[MAX_N + 1];
__device__ int    g_cursor[MAX_N];
__device__ int2   g_edges[MAX_E];

// ===========================================================================
// PTX helpers (legacy ops only: ldmatrix / mma.sync / cp.async -- all sm_80+)
// ===========================================================================
__device__ __forceinline__ uint32_t smem_u32(const void* p) {
    uint32_t a;
    asm("{ .reg .u64 t; cvta.to.shared.u64 t, %1; cvt.u32.u64 %0, t; }"
        : "=r"(a) : "l"(p));
    return a;
}

__device__ __forceinline__ void cp_async16(uint32_t dst, const void* src) {
    asm volatile("cp.async.cg.shared.global [%0], [%1], 16;"
                 :: "r"(dst), "l"(src) : "memory");
}
#define CP_COMMIT() asm volatile("cp.async.commit_group;" ::: "memory")
#define CP_WAIT0()  asm volatile("cp.async.wait_group 0;" ::: "memory")

__device__ __forceinline__ void ldsm_x4(uint32_t* r, uint32_t addr) {
    asm volatile("ldmatrix.sync.aligned.m8n8.x4.shared.b16 {%0,%1,%2,%3}, [%4];"
                 : "=r"(r[0]), "=r"(r[1]), "=r"(r[2]), "=r"(r[3]) : "r"(addr));
}

__device__ __forceinline__ void mma16816(float* c, const uint32_t* a, const uint32_t* b) {
    asm volatile(
        "mma.sync.aligned.m16n8k16.row.col.f32.f16.f16.f32 "
        "{%0,%1,%2,%3}, {%4,%5,%6,%7}, {%8,%9}, {%0,%1,%2,%3};"
        : "+f"(c[0]), "+f"(c[1]), "+f"(c[2]), "+f"(c[3])
        : "r"(a[0]), "r"(a[1]), "r"(a[2]), "r"(a[3]), "r"(b[0]), "r"(b[1]));
}

// ===========================================================================
// Weight transpose + fp16 convert: w[512][256] f32 -> g_wh[256][512] f16
// ===========================================================================
__global__ __launch_bounds__(1024)
void transpose_kernel(const float* __restrict__ w)
{
    __shared__ float tile[32][33];
    int n0 = blockIdx.x * 32;
    int k0 = blockIdx.y * 32;
    int tx = threadIdx.x & 31;
    int ty = threadIdx.x >> 5;
    tile[ty][tx] = w[(size_t)(k0 + ty) * OUT_DIM + n0 + tx];
    __syncthreads();
    g_wh[(size_t)(n0 + ty) * IN_DIM + k0 + tx] = __float2half(tile[tx][ty]);
}

// ===========================================================================
// fp16 HMMA GEMM: support = fp16(tanh?(x @ w))
// CTA tile 128(M) x 128(N), BK=32, 8 warps each 32x64, double-buffered.
// SMEM rows padded to 40 halves (80 B): ldmatrix rows hit disjoint bank quads.
// B fragment uses NON-trans ldmatrix: Bs is n-major (k contiguous), which is
// exactly the b0/b1 lane layout mma.row.col expects (pairs along k, n=lane>>2).
// ===========================================================================
#define GSTRIDE 40        // halves per SMEM row (32 data + 8 pad)
#define NSTAGE  16        // 512 / 32

__global__ __launch_bounds__(256, 2)
void gemm_hmma_kernel(const float* __restrict__ x,
                      const int*   __restrict__ active,
                      int N)
{
    __shared__ __half As[2][128 * GSTRIDE];   // 20 KB
    __shared__ __half Bs[2][128 * GSTRIDE];   // 20 KB

    const int tid  = threadIdx.x;
    const int wid  = tid >> 5;
    const int lane = tid & 31;
    const int block_col = blockIdx.x * 128;
    const int block_row = blockIdx.y * 128;

    const int wm = wid & 3;           // M band: wm*32
    const int wn = wid >> 2;          // N band: wn*64
    const int mbase = wm * 32;
    const int nbase = wn * 64;

    float acc[2][8][4];
    #pragma unroll
    for (int mt = 0; mt < 2; mt++)
        #pragma unroll
        for (int nt = 0; nt < 8; nt++)
            #pragma unroll
            for (int j = 0; j < 4; j++)
                acc[mt][nt][j] = 0.0f;

    // ---- A global-load mapping: thread -> row = tid>>1, qbase = (tid&1)*4 ----
    const int a_row   = tid >> 1;
    const int a_qbase = (tid & 1) * 4;
    int a_grow = block_row + a_row;
    if (a_grow >= N) a_grow = N - 1;          // clamp; result row unused
    const float* a_src_row = x + (size_t)a_grow * IN_DIM;

    // ---- B cp.async mapping: 2 chunks/thread, chunk cb -> n = cb>>2, q = cb&3
    const int b_n0 = (tid) >> 2;              // chunk 0 row
    const int b_q0 = tid & 3;
    const int b_n1 = (tid + 256) >> 2;        // chunk 1 row
    const int b_q1 = (tid + 256) & 3;
    const __half* wh0 = g_wh + (size_t)(block_col + b_n0) * IN_DIM + b_q0 * 8;
    const __half* wh1 = g_wh + (size_t)(block_col + b_n1) * IN_DIM + b_q1 * 8;

    auto load_B = [&](int s, int buf) {
        const int k0 = s * 32;
        uint32_t base = smem_u32(&Bs[buf][0]);
        cp_async16(base + (b_n0 * GSTRIDE + b_q0 * 8) * 2, wh0 + k0);
        cp_async16(base + (b_n1 * GSTRIDE + b_q1 * 8) * 2, wh1 + k0);
        CP_COMMIT();
    };

    auto store_A = [&](int buf, const float4* av) {
        __half* dst = &As[buf][a_row * GSTRIDE + a_qbase * 4];
        #pragma unroll
        for (int i = 0; i < 4; i++) {
            *(__half2*)(dst + i * 4)     = __float22half2_rn(make_float2(av[i].x, av[i].y));
            *(__half2*)(dst + i * 4 + 2) = __float22half2_rn(make_float2(av[i].z, av[i].w));
        }
    };

    // ---- prologue: stage 0 ----
    {
        load_B(0, 0);
        float4 av[4];
        #pragma unroll
        for (int i = 0; i < 4; i++)
            av[i] = *(const float4*)(a_src_row + (a_qbase + i) * 4);
        store_A(0, av);
        CP_WAIT0();
        __syncthreads();
    }

    int buf = 0;
    for (int s = 0; s < NSTAGE; s++) {
        // prefetch stage s+1
        float4 av[4];
        if (s < NSTAGE - 1) {
            const int k0n = (s + 1) * 32;
            #pragma unroll
            for (int i = 0; i < 4; i++)
                av[i] = *(const float4*)(a_src_row + k0n + (a_qbase + i) * 4);
            load_B(s + 1, buf ^ 1);
        }

        // compute stage s from SMEM[buf]
        const uint32_t aS = smem_u32(&As[buf][0]);
        const uint32_t bS = smem_u32(&Bs[buf][0]);
        const int ar   = lane & 7;
        const int amid = (lane >> 3) & 1;
        const int akh  = lane >> 4;
        #pragma unroll
        for (int ks = 0; ks < 2; ks++) {
            uint32_t afrag[2][4];
            #pragma unroll
            for (int mt = 0; mt < 2; mt++) {
                uint32_t addr = aS +
                    ((mbase + mt * 16 + amid * 8 + ar) * GSTRIDE + ks * 16 + akh * 8) * 2;
                ldsm_x4(afrag[mt], addr);
            }
            #pragma unroll
            for (int np = 0; np < 4; np++) {
                uint32_t bfrag[4];
                // non-trans: matrices [n0-7,k0-7],[n0-7,k8-15],[n8-15,k0-7],[n8-15,k8-15]
                uint32_t baddr = bS +
                    ((nbase + np * 16 + (lane >> 4) * 8 + (lane & 7)) * GSTRIDE
                     + ks * 16 + ((lane >> 3) & 1) * 8) * 2;
                ldsm_x4(bfrag, baddr);
                #pragma unroll
                for (int mt = 0; mt < 2; mt++) {
                    mma16816(acc[mt][np * 2],     afrag[mt], &bfrag[0]);
                    mma16816(acc[mt][np * 2 + 1], afrag[mt], &bfrag[2]);
                }
            }
        }

        if (s < NSTAGE - 1) {
            store_A(buf ^ 1, av);
            CP_WAIT0();
            __syncthreads();
            buf ^= 1;
        }
    }

    // ---- epilogue: tanh + fp16 store ----
    const bool act = (*active) != 0;
    #pragma unroll
    for (int mt = 0; mt < 2; mt++) {
        const int gm0 = block_row + mbase + mt * 16 + (lane >> 2);
        const int gm1 = gm0 + 8;
        #pragma unroll
        for (int nt = 0; nt < 8; nt++) {
            const int gn = block_col + nbase + nt * 8 + (lane & 3) * 2;
            float c0 = acc[mt][nt][0], c1 = acc[mt][nt][1];
            float c2 = acc[mt][nt][2], c3 = acc[mt][nt][3];
            if (act) { c0 = tanhf(c0); c1 = tanhf(c1); c2 = tanhf(c2); c3 = tanhf(c3); }
            if (gm0 < N)
                *(__half2*)&g_support[(size_t)gm0 * OUT_DIM + gn]
                    = __float22half2_rn(make_float2(c0, c1));
            if (gm1 < N)
                *(__half2*)&g_support[(size_t)gm1 * OUT_DIM + gn]
                    = __float22half2_rn(make_float2(c2, c3));
        }
    }
}

// ===========================================================================
// CSR build (unchanged)
// ===========================================================================
__global__ void zero_count_kernel(int N)
{
    int i = blockIdx.x * blockDim.x + threadIdx.x;
    if (i < N) g_count[i] = 0;
}

__global__ void hist_kernel(const int* __restrict__ rows, int E)
{
    int i = blockIdx.x * blockDim.x + threadIdx.x;
    int base = i * 4;
    if (base + 3 < E) {
        int4 r = *(const int4*)(rows + base);
        atomicAdd(&g_count[r.x], 1);
        atomicAdd(&g_count[r.y], 1);
        atomicAdd(&g_count[r.z], 1);
        atomicAdd(&g_count[r.w], 1);
    } else {
        for (int j = base; j < E; j++) atomicAdd(&g_count[rows[j]], 1);
    }
}

__global__ __launch_bounds__(1024)
void scan_kernel(int N)
{
    __shared__ int carry;
    __shared__ int warp_sums[32];
    const int tid  = threadIdx.x;
    const int lane = tid & 31;
    const int wid  = tid >> 5;

    if (tid == 0) carry = 0;
    __syncthreads();

    for (int base = 0; base < N; base += 1024) {
        int i = base + tid;
        int v = (i < N) ? g_count[i] : 0;

        int s = v;
        #pragma unroll
        for (int off = 1; off < 32; off <<= 1) {
            int t = __shfl_up_sync(0xFFFFFFFFu, s, off);
            if (lane >= off) s += t;
        }
        if (lane == 31) warp_sums[wid] = s;
        __syncthreads();

        if (wid == 0) {
            int ws = warp_sums[lane];
            #pragma unroll
            for (int off = 1; off < 32; off <<= 1) {
                int t = __shfl_up_sync(0xFFFFFFFFu, ws, off);
                if (lane >= off) ws += t;
            }
            warp_sums[lane] = ws;
        }
        __syncthreads();

        int excl = carry + (wid > 0 ? warp_sums[wid - 1] : 0) + (s - v);
        if (i < N) {
            g_offset[i] = excl;
            g_cursor[i] = excl;
        }
        __syncthreads();
        if (tid == 0) carry += warp_sums[31];
        __syncthreads();
    }
    if (tid == 0) g_offset[N] = carry;
}

__global__ void reorder_kernel(const int* __restrict__ rows,
                               const int* __restrict__ cols,
                               const float* __restrict__ vals,
                               int E)
{
    int i = blockIdx.x * blockDim.x + threadIdx.x;
    if (i >= E) return;
    int r = rows[i];
    int pos = atomicAdd(&g_cursor[r], 1);
    g_edges[pos] = make_int2(cols[i], __float_as_int(vals[i]));
}

// ===========================================================================
// Gather SpMM (unchanged)
// ===========================================================================
__device__ __forceinline__ void fma8_h(const uint4 p, float v, float* acc)
{
    float2 f0 = __half22float2(*(const __half2*)&p.x);
    float2 f1 = __half22float2(*(const __half2*)&p.y);
    float2 f2 = __half22float2(*(const __half2*)&p.z);
    float2 f3 = __half22float2(*(const __half2*)&p.w);
    acc[0] = fmaf(v, f0.x, acc[0]);
    acc[1] = fmaf(v, f0.y, acc[1]);
    acc[2] = fmaf(v, f1.x, acc[2]);
    acc[3] = fmaf(v, f1.y, acc[3]);
    acc[4] = fmaf(v, f2.x, acc[4]);
    acc[5] = fmaf(v, f2.y, acc[5]);
    acc[6] = fmaf(v, f3.x, acc[6]);
    acc[7] = fmaf(v, f3.y, acc[7]);
}

__global__ __launch_bounds__(256)
void gather_kernel(float* __restrict__ out, int N)
{
    int warp = (blockIdx.x * blockDim.x + threadIdx.x) >> 5;
    int lane = threadIdx.x & 31;
    if (warp >= N) return;

    int beg = g_offset[warp];
    int end = g_offset[warp + 1];

    float acc[8];
    #pragma unroll
    for (int j = 0; j < 8; j++) acc[j] = 0.0f;

    int e = beg;
    for (; e + 1 < end; e += 2) {
        int2 ed0 = g_edges[e];
        int2 ed1 = g_edges[e + 1];
        const uint4* s0 = (const uint4*)(g_support + (size_t)ed0.x * OUT_DIM);
        const uint4* s1 = (const uint4*)(g_support + (size_t)ed1.x * OUT_DIM);
        uint4 p0 = s0[lane];
        uint4 p1 = s1[lane];
        fma8_h(p0, __int_as_float(ed0.y), acc);
        fma8_h(p1, __int_as_float(ed1.y), acc);
    }
    if (e < end) {
        int2 ed = g_edges[e];
        const uint4* s = (const uint4*)(g_support + (size_t)ed.x * OUT_DIM);
        uint4 p = s[lane];
        fma8_h(p, __int_as_float(ed.y), acc);
    }

    float* dst = out + (size_t)warp * OUT_DIM + lane * 8;
    *(float4*)(dst)     = make_float4(acc[0], acc[1], acc[2], acc[3]);
    *(float4*)(dst + 4) = make_float4(acc[4], acc[5], acc[6], acc[7]);
}

// ===========================================================================
// Launch
// ===========================================================================
extern "C" void kernel_launch(void* const* d_in, const int* in_sizes, int n_in,
                              void* d_out, int out_size)
{
    const float* x      = (const float*)d_in[0];
    const float* w      = (const float*)d_in[1];
    const int*   erows  = (const int*)d_in[2];
    const int*   ecols  = (const int*)d_in[3];
    const float* evals  = (const float*)d_in[4];
    const int*   active = (const int*)d_in[5];
    float*       out    = (float*)d_out;

    const int N = in_sizes[0] / IN_DIM;
    const int E = in_sizes[2];

    // weight transpose + fp16 convert
    dim3 tgrid(OUT_DIM / 32, IN_DIM / 32);
    transpose_kernel<<<tgrid, 1024>>>(w);

    // CSR build
    zero_count_kernel<<<(N + 255) / 256, 256>>>(N);
    hist_kernel<<<((E + 3) / 4 + 255) / 256, 256>>>(erows, E);
    scan_kernel<<<1, 1024>>>(N);
    reorder_kernel<<<(E + 255) / 256, 256>>>(erows, ecols, evals, E);

    // HMMA fp16 GEMM: g_support = fp16(tanh?(x @ w))
    dim3 ggrid(OUT_DIM / 128, (N + 127) / 128);
    gemm_hmma_kernel<<<ggrid, 256>>>(x, active, N);

    // Gather SpMM
    int gblocks = (N * 32 + 255) / 256;
    gather_kernel<<<gblocks, 256>>>(out, N);
}

// round 8
// speedup vs baseline: 4.5674x; 1.1901x over previous
#include <cuda_runtime.h>
#include <cuda_fp16.h>
#include <cstdint>

// Problem constants: N=100000, IN=512, OUT=256, E=3.2M
#define IN_DIM  512
#define OUT_DIM 256
#define MAX_N   100000
#define MAX_E   3200000
#define SCAN_CHUNK 1024
#define SCAN_BLOCKS ((MAX_N + SCAN_CHUNK - 1) / SCAN_CHUNK)   // 98

// Scratch (device globals -- no runtime allocation allowed)
__device__ __half g_support[(size_t)MAX_N * OUT_DIM];  // 51.2 MB fp16
__device__ __half g_wh[(size_t)OUT_DIM * IN_DIM];      // w^T [256][512] fp16, K-major
__device__ int    g_count[MAX_N];
__device__ int    g_offset[MAX_N + 1];
__device__ int    g_cursor[MAX_N];
__device__ int    g_bsum[SCAN_BLOCKS + 1];
__device__ int2   g_edges[MAX_E];

// ===========================================================================
// PTX helpers (legacy ops only: ldmatrix / mma.sync / cp.async -- all sm_80+)
// ===========================================================================
__device__ __forceinline__ uint32_t smem_u32(const void* p) {
    uint32_t a;
    asm("{ .reg .u64 t; cvta.to.shared.u64 t, %1; cvt.u32.u64 %0, t; }"
        : "=r"(a) : "l"(p));
    return a;
}

__device__ __forceinline__ void cp_async16(uint32_t dst, const void* src) {
    asm volatile("cp.async.cg.shared.global [%0], [%1], 16;"
                 :: "r"(dst), "l"(src) : "memory");
}
#define CP_COMMIT() asm volatile("cp.async.commit_group;" ::: "memory")
#define CP_WAIT0()  asm volatile("cp.async.wait_group 0;" ::: "memory")

__device__ __forceinline__ void ldsm_x4(uint32_t* r, uint32_t addr) {
    asm volatile("ldmatrix.sync.aligned.m8n8.x4.shared.b16 {%0,%1,%2,%3}, [%4];"
                 : "=r"(r[0]), "=r"(r[1]), "=r"(r[2]), "=r"(r[3]) : "r"(addr));
}

__device__ __forceinline__ void mma16816(float* c, const uint32_t* a, const uint32_t* b) {
    asm volatile(
        "mma.sync.aligned.m16n8k16.row.col.f32.f16.f16.f32 "
        "{%0,%1,%2,%3}, {%4,%5,%6,%7}, {%8,%9}, {%0,%1,%2,%3};"
        : "+f"(c[0]), "+f"(c[1]), "+f"(c[2]), "+f"(c[3])
        : "r"(a[0]), "r"(a[1]), "r"(a[2]), "r"(a[3]), "r"(b[0]), "r"(b[1]));
}

// ===========================================================================
// Weight transpose + fp16 convert: w[512][256] f32 -> g_wh[256][512] f16
// ===========================================================================
__global__ __launch_bounds__(1024)
void transpose_kernel(const float* __restrict__ w)
{
    __shared__ float tile[32][33];
    int n0 = blockIdx.x * 32;
    int k0 = blockIdx.y * 32;
    int tx = threadIdx.x & 31;
    int ty = threadIdx.x >> 5;
    tile[ty][tx] = w[(size_t)(k0 + ty) * OUT_DIM + n0 + tx];
    __syncthreads();
    g_wh[(size_t)(n0 + ty) * IN_DIM + k0 + tx] = __float2half(tile[tx][ty]);
}

// ===========================================================================
// fp16 HMMA GEMM: support = fp16(tanh?(x @ w))   (unchanged from R7)
// ===========================================================================
#define GSTRIDE 40        // halves per SMEM row (32 data + 8 pad)
#define NSTAGE  16        // 512 / 32

__global__ __launch_bounds__(256, 2)
void gemm_hmma_kernel(const float* __restrict__ x,
                      const int*   __restrict__ active,
                      int N)
{
    __shared__ __half As[2][128 * GSTRIDE];   // 20 KB
    __shared__ __half Bs[2][128 * GSTRIDE];   // 20 KB

    const int tid  = threadIdx.x;
    const int wid  = tid >> 5;
    const int lane = tid & 31;
    const int block_col = blockIdx.x * 128;
    const int block_row = blockIdx.y * 128;

    const int wm = wid & 3;
    const int wn = wid >> 2;
    const int mbase = wm * 32;
    const int nbase = wn * 64;

    float acc[2][8][4];
    #pragma unroll
    for (int mt = 0; mt < 2; mt++)
        #pragma unroll
        for (int nt = 0; nt < 8; nt++)
            #pragma unroll
            for (int j = 0; j < 4; j++)
                acc[mt][nt][j] = 0.0f;

    const int a_row   = tid >> 1;
    const int a_qbase = (tid & 1) * 4;
    int a_grow = block_row + a_row;
    if (a_grow >= N) a_grow = N - 1;
    const float* a_src_row = x + (size_t)a_grow * IN_DIM;

    const int b_n0 = (tid) >> 2;
    const int b_q0 = tid & 3;
    const int b_n1 = (tid + 256) >> 2;
    const int b_q1 = (tid + 256) & 3;
    const __half* wh0 = g_wh + (size_t)(block_col + b_n0) * IN_DIM + b_q0 * 8;
    const __half* wh1 = g_wh + (size_t)(block_col + b_n1) * IN_DIM + b_q1 * 8;

    auto load_B = [&](int s, int buf) {
        const int k0 = s * 32;
        uint32_t base = smem_u32(&Bs[buf][0]);
        cp_async16(base + (b_n0 * GSTRIDE + b_q0 * 8) * 2, wh0 + k0);
        cp_async16(base + (b_n1 * GSTRIDE + b_q1 * 8) * 2, wh1 + k0);
        CP_COMMIT();
    };

    auto store_A = [&](int buf, const float4* av) {
        __half* dst = &As[buf][a_row * GSTRIDE + a_qbase * 4];
        #pragma unroll
        for (int i = 0; i < 4; i++) {
            *(__half2*)(dst + i * 4)     = __float22half2_rn(make_float2(av[i].x, av[i].y));
            *(__half2*)(dst + i * 4 + 2) = __float22half2_rn(make_float2(av[i].z, av[i].w));
        }
    };

    {
        load_B(0, 0);
        float4 av[4];
        #pragma unroll
        for (int i = 0; i < 4; i++)
            av[i] = *(const float4*)(a_src_row + (a_qbase + i) * 4);
        store_A(0, av);
        CP_WAIT0();
        __syncthreads();
    }

    int buf = 0;
    for (int s = 0; s < NSTAGE; s++) {
        float4 av[4];
        if (s < NSTAGE - 1) {
            const int k0n = (s + 1) * 32;
            #pragma unroll
            for (int i = 0; i < 4; i++)
                av[i] = *(const float4*)(a_src_row + k0n + (a_qbase + i) * 4);
            load_B(s + 1, buf ^ 1);
        }

        const uint32_t aS = smem_u32(&As[buf][0]);
        const uint32_t bS = smem_u32(&Bs[buf][0]);
        const int ar   = lane & 7;
        const int amid = (lane >> 3) & 1;
        const int akh  = lane >> 4;
        #pragma unroll
        for (int ks = 0; ks < 2; ks++) {
            uint32_t afrag[2][4];
            #pragma unroll
            for (int mt = 0; mt < 2; mt++) {
                uint32_t addr = aS +
                    ((mbase + mt * 16 + amid * 8 + ar) * GSTRIDE + ks * 16 + akh * 8) * 2;
                ldsm_x4(afrag[mt], addr);
            }
            #pragma unroll
            for (int np = 0; np < 4; np++) {
                uint32_t bfrag[4];
                uint32_t baddr = bS +
                    ((nbase + np * 16 + (lane >> 4) * 8 + (lane & 7)) * GSTRIDE
                     + ks * 16 + ((lane >> 3) & 1) * 8) * 2;
                ldsm_x4(bfrag, baddr);
                #pragma unroll
                for (int mt = 0; mt < 2; mt++) {
                    mma16816(acc[mt][np * 2],     afrag[mt], &bfrag[0]);
                    mma16816(acc[mt][np * 2 + 1], afrag[mt], &bfrag[2]);
                }
            }
        }

        if (s < NSTAGE - 1) {
            store_A(buf ^ 1, av);
            CP_WAIT0();
            __syncthreads();
            buf ^= 1;
        }
    }

    const bool act = (*active) != 0;
    #pragma unroll
    for (int mt = 0; mt < 2; mt++) {
        const int gm0 = block_row + mbase + mt * 16 + (lane >> 2);
        const int gm1 = gm0 + 8;
        #pragma unroll
        for (int nt = 0; nt < 8; nt++) {
            const int gn = block_col + nbase + nt * 8 + (lane & 3) * 2;
            float c0 = acc[mt][nt][0], c1 = acc[mt][nt][1];
            float c2 = acc[mt][nt][2], c3 = acc[mt][nt][3];
            if (act) { c0 = tanhf(c0); c1 = tanhf(c1); c2 = tanhf(c2); c3 = tanhf(c3); }
            if (gm0 < N)
                *(__half2*)&g_support[(size_t)gm0 * OUT_DIM + gn]
                    = __float22half2_rn(make_float2(c0, c1));
            if (gm1 < N)
                *(__half2*)&g_support[(size_t)gm1 * OUT_DIM + gn]
                    = __float22half2_rn(make_float2(c2, c3));
        }
    }
}

// ===========================================================================
// CSR build: zero -> hist -> 3-kernel parallel scan -> reorder
// ===========================================================================
__global__ void zero_count_kernel(int N)
{
    int i = blockIdx.x * blockDim.x + threadIdx.x;
    if (i < N) g_count[i] = 0;
}

__global__ void hist_kernel(const int* __restrict__ rows, int E)
{
    int i = blockIdx.x * blockDim.x + threadIdx.x;
    int base = i * 4;
    if (base + 3 < E) {
        int4 r = *(const int4*)(rows + base);
        atomicAdd(&g_count[r.x], 1);
        atomicAdd(&g_count[r.y], 1);
        atomicAdd(&g_count[r.z], 1);
        atomicAdd(&g_count[r.w], 1);
    } else {
        for (int j = base; j < E; j++) atomicAdd(&g_count[rows[j]], 1);
    }
}

// block-wide exclusive scan helper: returns exclusive prefix of v for this
// thread; total of the block left in *total (valid for all threads).
__device__ __forceinline__ int block_excl_scan(int v, int* warp_sums, int* total)
{
    const int lane = threadIdx.x & 31;
    const int wid  = threadIdx.x >> 5;
    const int nw   = blockDim.x >> 5;

    int s = v;
    #pragma unroll
    for (int off = 1; off < 32; off <<= 1) {
        int t = __shfl_up_sync(0xFFFFFFFFu, s, off);
        if (lane >= off) s += t;
    }
    if (lane == 31) warp_sums[wid] = s;
    __syncthreads();
    if (wid == 0) {
        int ws = (lane < nw) ? warp_sums[lane] : 0;
        #pragma unroll
        for (int off = 1; off < 32; off <<= 1) {
            int t = __shfl_up_sync(0xFFFFFFFFu, ws, off);
            if (lane >= off) ws += t;
        }
        if (lane < nw) warp_sums[lane] = ws;
    }
    __syncthreads();
    *total = warp_sums[nw - 1];
    return (wid > 0 ? warp_sums[wid - 1] : 0) + (s - v);
}

// part1: per-block exclusive scan of g_count chunk -> g_offset; block total -> g_bsum
__global__ __launch_bounds__(SCAN_CHUNK)
void scan_part1_kernel(int N)
{
    __shared__ int warp_sums[32];
    int i = blockIdx.x * SCAN_CHUNK + threadIdx.x;
    int v = (i < N) ? g_count[i] : 0;
    int total;
    int excl = block_excl_scan(v, warp_sums, &total);
    if (i < N) g_offset[i] = excl;
    if (threadIdx.x == 0) g_bsum[blockIdx.x] = total;
}

// part2: single small block scans the block sums in place (exclusive) and
// writes the grand total to g_offset[N].
__global__ __launch_bounds__(128)
void scan_part2_kernel(int nblocks, int N)
{
    __shared__ int warp_sums[32];
    int v = (threadIdx.x < nblocks) ? g_bsum[threadIdx.x] : 0;
    int total;
    int excl = block_excl_scan(v, warp_sums, &total);
    if (threadIdx.x < nblocks) g_bsum[threadIdx.x] = excl;
    if (threadIdx.x == 0) g_offset[N] = total;
}

// part3: add block offsets; materialize g_offset and g_cursor
__global__ __launch_bounds__(SCAN_CHUNK)
void scan_part3_kernel(int N)
{
    int i = blockIdx.x * SCAN_CHUNK + threadIdx.x;
    if (i < N) {
        int o = g_offset[i] + g_bsum[blockIdx.x];
        g_offset[i] = o;
        g_cursor[i] = o;
    }
}

__global__ void reorder_kernel(const int* __restrict__ rows,
                               const int* __restrict__ cols,
                               const float* __restrict__ vals,
                               int E)
{
    int i = blockIdx.x * blockDim.x + threadIdx.x;
    if (i >= E) return;
    int r = rows[i];
    int pos = atomicAdd(&g_cursor[r], 1);
    g_edges[pos] = make_int2(cols[i], __float_as_int(vals[i]));
}

// ===========================================================================
// Gather SpMM (unchanged)
// ===========================================================================
__device__ __forceinline__ void fma8_h(const uint4 p, float v, float* acc)
{
    float2 f0 = __half22float2(*(const __half2*)&p.x);
    float2 f1 = __half22float2(*(const __half2*)&p.y);
    float2 f2 = __half22float2(*(const __half2*)&p.z);
    float2 f3 = __half22float2(*(const __half2*)&p.w);
    acc[0] = fmaf(v, f0.x, acc[0]);
    acc[1] = fmaf(v, f0.y, acc[1]);
    acc[2] = fmaf(v, f1.x, acc[2]);
    acc[3] = fmaf(v, f1.y, acc[3]);
    acc[4] = fmaf(v, f2.x, acc[4]);
    acc[5] = fmaf(v, f2.y, acc[5]);
    acc[6] = fmaf(v, f3.x, acc[6]);
    acc[7] = fmaf(v, f3.y, acc[7]);
}

__global__ __launch_bounds__(256)
void gather_kernel(float* __restrict__ out, int N)
{
    int warp = (blockIdx.x * blockDim.x + threadIdx.x) >> 5;
    int lane = threadIdx.x & 31;
    if (warp >= N) return;

    int beg = g_offset[warp];
    int end = g_offset[warp + 1];

    float acc[8];
    #pragma unroll
    for (int j = 0; j < 8; j++) acc[j] = 0.0f;

    int e = beg;
    for (; e + 1 < end; e += 2) {
        int2 ed0 = g_edges[e];
        int2 ed1 = g_edges[e + 1];
        const uint4* s0 = (const uint4*)(g_support + (size_t)ed0.x * OUT_DIM);
        const uint4* s1 = (const uint4*)(g_support + (size_t)ed1.x * OUT_DIM);
        uint4 p0 = s0[lane];
        uint4 p1 = s1[lane];
        fma8_h(p0, __int_as_float(ed0.y), acc);
        fma8_h(p1, __int_as_float(ed1.y), acc);
    }
    if (e < end) {
        int2 ed = g_edges[e];
        const uint4* s = (const uint4*)(g_support + (size_t)ed.x * OUT_DIM);
        uint4 p = s[lane];
        fma8_h(p, __int_as_float(ed.y), acc);
    }

    float* dst = out + (size_t)warp * OUT_DIM + lane * 8;
    *(float4*)(dst)     = make_float4(acc[0], acc[1], acc[2], acc[3]);
    *(float4*)(dst + 4) = make_float4(acc[4], acc[5], acc[6], acc[7]);
}

// ===========================================================================
// Launch
// ===========================================================================
extern "C" void kernel_launch(void* const* d_in, const int* in_sizes, int n_in,
                              void* d_out, int out_size)
{
    const float* x      = (const float*)d_in[0];
    const float* w      = (const float*)d_in[1];
    const int*   erows  = (const int*)d_in[2];
    const int*   ecols  = (const int*)d_in[3];
    const float* evals  = (const float*)d_in[4];
    const int*   active = (const int*)d_in[5];
    float*       out    = (float*)d_out;

    const int N = in_sizes[0] / IN_DIM;
    const int E = in_sizes[2];
    const int nsb = (N + SCAN_CHUNK - 1) / SCAN_CHUNK;

    // weight transpose + fp16 convert
    dim3 tgrid(OUT_DIM / 32, IN_DIM / 32);
    transpose_kernel<<<tgrid, 1024>>>(w);

    // CSR build
    zero_count_kernel<<<(N + 255) / 256, 256>>>(N);
    hist_kernel<<<((E + 3) / 4 + 255) / 256, 256>>>(erows, E);
    scan_part1_kernel<<<nsb, SCAN_CHUNK>>>(N);
    scan_part2_kernel<<<1, 128>>>(nsb, N);
    scan_part3_kernel<<<nsb, SCAN_CHUNK>>>(N);
    reorder_kernel<<<(E + 255) / 256, 256>>>(erows, ecols, evals, E);

    // HMMA fp16 GEMM: g_support = fp16(tanh?(x @ w))
    dim3 ggrid(OUT_DIM / 128, (N + 127) / 128);
    gemm_hmma_kernel<<<ggrid, 256>>>(x, active, N);

    // Gather SpMM
    int gblocks = (N * 32 + 255) / 256;
    gather_kernel<<<gblocks, 256>>>(out, N);
}

// round 9
// speedup vs baseline: 4.9112x; 1.0753x over previous
#include <cuda_runtime.h>
#include <cuda_fp16.h>
#include <cstdint>

// Problem constants: N=100000, IN=512, OUT=256, E=3.2M
#define IN_DIM  512
#define OUT_DIM 256
#define MAX_N   100000
#define MAX_E   3200000
#define SCAN_CHUNK 1024
#define SCAN_BLOCKS ((MAX_N + SCAN_CHUNK - 1) / SCAN_CHUNK)   // 98

// Scratch (device globals -- no runtime allocation allowed)
__device__ __half g_support[(size_t)MAX_N * OUT_DIM];  // 51.2 MB fp16
__device__ __half g_wh[(size_t)OUT_DIM * IN_DIM];      // w^T [256][512] fp16, K-major
__device__ int    g_count[MAX_N];
__device__ int    g_offset[MAX_N + 1];
__device__ int    g_cursor[MAX_N];
__device__ int    g_bsum[SCAN_BLOCKS + 1];
__device__ int2   g_edges[MAX_E];

// ===========================================================================
// PTX helpers
// ===========================================================================
__device__ __forceinline__ uint32_t smem_u32(const void* p) {
    uint32_t a;
    asm("{ .reg .u64 t; cvta.to.shared.u64 t, %1; cvt.u32.u64 %0, t; }"
        : "=r"(a) : "l"(p));
    return a;
}

__device__ __forceinline__ void cp_async16(uint32_t dst, const void* src) {
    asm volatile("cp.async.cg.shared.global [%0], [%1], 16;"
                 :: "r"(dst), "l"(src) : "memory");
}
#define CP_COMMIT() asm volatile("cp.async.commit_group;" ::: "memory")
#define CP_WAIT0()  asm volatile("cp.async.wait_group 0;" ::: "memory")

__device__ __forceinline__ void ldsm_x4(uint32_t* r, uint32_t addr) {
    asm volatile("ldmatrix.sync.aligned.m8n8.x4.shared.b16 {%0,%1,%2,%3}, [%4];"
                 : "=r"(r[0]), "=r"(r[1]), "=r"(r[2]), "=r"(r[3]) : "r"(addr));
}

__device__ __forceinline__ void mma16816(float* c, const uint32_t* a, const uint32_t* b) {
    asm volatile(
        "mma.sync.aligned.m16n8k16.row.col.f32.f16.f16.f32 "
        "{%0,%1,%2,%3}, {%4,%5,%6,%7}, {%8,%9}, {%0,%1,%2,%3};"
        : "+f"(c[0]), "+f"(c[1]), "+f"(c[2]), "+f"(c[3])
        : "r"(a[0]), "r"(a[1]), "r"(a[2]), "r"(a[3]), "r"(b[0]), "r"(b[1]));
}

// ===========================================================================
// Prelude: transpose+convert weight (blocks 0-127) || zero g_count (rest)
// ===========================================================================
#define TRANS_BLOCKS 128          // (OUT/32) * (IN/32) = 8*16

__global__ __launch_bounds__(256)
void prelude_kernel(const float* __restrict__ w, int N)
{
    __shared__ float tile[32][33];
    const int tid = threadIdx.x;
    if (blockIdx.x < TRANS_BLOCKS) {
        int n0 = (blockIdx.x & 7) * 32;
        int k0 = (blockIdx.x >> 3) * 32;
        int tx = tid & 31;
        int ty = tid >> 5;              // 0..7
        #pragma unroll
        for (int i = 0; i < 4; i++)
            tile[ty + 8 * i][tx] = w[(size_t)(k0 + ty + 8 * i) * OUT_DIM + n0 + tx];
        __syncthreads();
        #pragma unroll
        for (int i = 0; i < 4; i++)
            g_wh[(size_t)(n0 + ty + 8 * i) * IN_DIM + k0 + tx]
                = __float2half(tile[tx][ty + 8 * i]);
    } else {
        int i = (blockIdx.x - TRANS_BLOCKS) * 256 + tid;
        if (i < N) g_count[i] = 0;
    }
}

// ===========================================================================
// Fused: HMMA GEMM (blocks [0, gemm_blocks)) || histogram (rest).
// GEMM: CTA tile 64(M) x 256(N) -- single pass over N, A read ONCE.
// 8 warps, each 32x64; BK=32; double-buffered dynamic SMEM (50 KB).
// ===========================================================================
#define GSTRIDE 40                 // halves per SMEM row (32 data + 8 pad)
#define NSTAGE  16                 // 512 / 32
#define OFF_A0  0
#define OFF_A1  (64 * GSTRIDE * 2)                 // 5120
#define OFF_B0  (2 * 64 * GSTRIDE * 2)             // 10240
#define OFF_B1  (OFF_B0 + 256 * GSTRIDE * 2)       // 30720
#define GEMM_SMEM (OFF_B1 + 256 * GSTRIDE * 2)     // 51200
#define HIST_BLOCKS 1024

__global__ __launch_bounds__(256, 2)
void gemm_hist_kernel(const float* __restrict__ x,
                      const int*   __restrict__ active,
                      const int*   __restrict__ rows,
                      int N, int E, int gemm_blocks)
{
    extern __shared__ char dsm[];
    const int tid  = threadIdx.x;

    if ((int)blockIdx.x >= gemm_blocks) {
        // ---------------- histogram body (grid-stride, int4) ----------------
        const int hb   = blockIdx.x - gemm_blocks;
        const int span = HIST_BLOCKS * 256;
        const int qid  = hb * 256 + tid;
        const int nquads = E >> 2;
        for (int q = qid; q < nquads; q += span) {
            int4 r = *(const int4*)(rows + q * 4);
            atomicAdd(&g_count[r.x], 1);
            atomicAdd(&g_count[r.y], 1);
            atomicAdd(&g_count[r.z], 1);
            atomicAdd(&g_count[r.w], 1);
        }
        if (qid == 0)
            for (int j = nquads * 4; j < E; j++) atomicAdd(&g_count[rows[j]], 1);
        return;
    }

    // -------------------------- GEMM body -----------------------------------
    const int wid  = tid >> 5;
    const int lane = tid & 31;
    const int block_row = blockIdx.x * 64;

    const int mbase = (wid & 1) * 32;
    const int nbase = (wid >> 1) * 64;

    float acc[2][8][4];
    #pragma unroll
    for (int mt = 0; mt < 2; mt++)
        #pragma unroll
        for (int nt = 0; nt < 8; nt++)
            #pragma unroll
            for (int j = 0; j < 4; j++)
                acc[mt][nt][j] = 0.0f;

    // A: 64 rows x 32 f32/stage = 512 float4-chunks; 2 per thread
    const int a_r0 = tid >> 3;             // 0..31
    const int a_r1 = (tid + 256) >> 3;     // 32..63
    const int a_q  = tid & 7;              // 0..7 -> col q*4
    int ag0 = block_row + a_r0; if (ag0 >= N) ag0 = N - 1;
    int ag1 = block_row + a_r1; if (ag1 >= N) ag1 = N - 1;
    const float* ap0 = x + (size_t)ag0 * IN_DIM + a_q * 4;
    const float* ap1 = x + (size_t)ag1 * IN_DIM + a_q * 4;

    // B: 256 rows x 32 halves/stage = 1024 16B-chunks; 4 per thread
    int b_n[4], b_q[4];
    const __half* bp[4];
    #pragma unroll
    for (int i = 0; i < 4; i++) {
        int c = tid + 256 * i;
        b_n[i] = c >> 2;
        b_q[i] = c & 3;
        bp[i] = g_wh + (size_t)b_n[i] * IN_DIM + b_q[i] * 8;
    }

    const uint32_t aS[2] = { smem_u32(dsm + OFF_A0), smem_u32(dsm + OFF_A1) };
    const uint32_t bS[2] = { smem_u32(dsm + OFF_B0), smem_u32(dsm + OFF_B1) };

    auto load_B = [&](int s, int buf) {
        const int k0 = s * 32;
        #pragma unroll
        for (int i = 0; i < 4; i++)
            cp_async16(bS[buf] + (b_n[i] * GSTRIDE + b_q[i] * 8) * 2, bp[i] + k0);
        CP_COMMIT();
    };

    auto store_A = [&](int buf, const float4 av0, const float4 av1) {
        __half* dA = (__half*)(dsm + (buf ? OFF_A1 : OFF_A0));
        __half* d0 = dA + a_r0 * GSTRIDE + a_q * 4;
        __half* d1 = dA + a_r1 * GSTRIDE + a_q * 4;
        *(__half2*)(d0)     = __float22half2_rn(make_float2(av0.x, av0.y));
        *(__half2*)(d0 + 2) = __float22half2_rn(make_float2(av0.z, av0.w));
        *(__half2*)(d1)     = __float22half2_rn(make_float2(av1.x, av1.y));
        *(__half2*)(d1 + 2) = __float22half2_rn(make_float2(av1.z, av1.w));
    };

    // prologue: stage 0
    {
        load_B(0, 0);
        float4 av0 = *(const float4*)(ap0);
        float4 av1 = *(const float4*)(ap1);
        store_A(0, av0, av1);
        CP_WAIT0();
        __syncthreads();
    }

    int buf = 0;
    for (int s = 0; s < NSTAGE; s++) {
        float4 av0, av1;
        if (s < NSTAGE - 1) {
            const int k0n = (s + 1) * 32;
            av0 = *(const float4*)(ap0 + k0n);
            av1 = *(const float4*)(ap1 + k0n);
            load_B(s + 1, buf ^ 1);
        }

        const int ar   = lane & 7;
        const int amid = (lane >> 3) & 1;
        const int akh  = lane >> 4;
        #pragma unroll
        for (int ks = 0; ks < 2; ks++) {
            uint32_t afrag[2][4];
            #pragma unroll
            for (int mt = 0; mt < 2; mt++) {
                uint32_t addr = aS[buf] +
                    ((mbase + mt * 16 + amid * 8 + ar) * GSTRIDE + ks * 16 + akh * 8) * 2;
                ldsm_x4(afrag[mt], addr);
            }
            #pragma unroll
            for (int np = 0; np < 4; np++) {
                uint32_t bfrag[4];
                uint32_t baddr = bS[buf] +
                    ((nbase + np * 16 + (lane >> 4) * 8 + (lane & 7)) * GSTRIDE
                     + ks * 16 + ((lane >> 3) & 1) * 8) * 2;
                ldsm_x4(bfrag, baddr);
                #pragma unroll
                for (int mt = 0; mt < 2; mt++) {
                    mma16816(acc[mt][np * 2],     afrag[mt], &bfrag[0]);
                    mma16816(acc[mt][np * 2 + 1], afrag[mt], &bfrag[2]);
                }
            }
        }

        if (s < NSTAGE - 1) {
            store_A(buf ^ 1, av0, av1);
            CP_WAIT0();
            __syncthreads();
            buf ^= 1;
        }
    }

    // epilogue: tanh + fp16 store
    const bool act = (*active) != 0;
    #pragma unroll
    for (int mt = 0; mt < 2; mt++) {
        const int gm0 = block_row + mbase + mt * 16 + (lane >> 2);
        const int gm1 = gm0 + 8;
        #pragma unroll
        for (int nt = 0; nt < 8; nt++) {
            const int gn = nbase + nt * 8 + (lane & 3) * 2;
            float c0 = acc[mt][nt][0], c1 = acc[mt][nt][1];
            float c2 = acc[mt][nt][2], c3 = acc[mt][nt][3];
            if (act) { c0 = tanhf(c0); c1 = tanhf(c1); c2 = tanhf(c2); c3 = tanhf(c3); }
            if (gm0 < N)
                *(__half2*)&g_support[(size_t)gm0 * OUT_DIM + gn]
                    = __float22half2_rn(make_float2(c0, c1));
            if (gm1 < N)
                *(__half2*)&g_support[(size_t)gm1 * OUT_DIM + gn]
                    = __float22half2_rn(make_float2(c2, c3));
        }
    }
}

// ===========================================================================
// Parallel scan (unchanged from R8)
// ===========================================================================
__device__ __forceinline__ int block_excl_scan(int v, int* warp_sums, int* total)
{
    const int lane = threadIdx.x & 31;
    const int wid  = threadIdx.x >> 5;
    const int nw   = blockDim.x >> 5;

    int s = v;
    #pragma unroll
    for (int off = 1; off < 32; off <<= 1) {
        int t = __shfl_up_sync(0xFFFFFFFFu, s, off);
        if (lane >= off) s += t;
    }
    if (lane == 31) warp_sums[wid] = s;
    __syncthreads();
    if (wid == 0) {
        int ws = (lane < nw) ? warp_sums[lane] : 0;
        #pragma unroll
        for (int off = 1; off < 32; off <<= 1) {
            int t = __shfl_up_sync(0xFFFFFFFFu, ws, off);
            if (lane >= off) ws += t;
        }
        if (lane < nw) warp_sums[lane] = ws;
    }
    __syncthreads();
    *total = warp_sums[nw - 1];
    return (wid > 0 ? warp_sums[wid - 1] : 0) + (s - v);
}

__global__ __launch_bounds__(SCAN_CHUNK)
void scan_part1_kernel(int N)
{
    __shared__ int warp_sums[32];
    int i = blockIdx.x * SCAN_CHUNK + threadIdx.x;
    int v = (i < N) ? g_count[i] : 0;
    int total;
    int excl = block_excl_scan(v, warp_sums, &total);
    if (i < N) g_offset[i] = excl;
    if (threadIdx.x == 0) g_bsum[blockIdx.x] = total;
}

__global__ __launch_bounds__(128)
void scan_part2_kernel(int nblocks, int N)
{
    __shared__ int warp_sums[32];
    int v = (threadIdx.x < nblocks) ? g_bsum[threadIdx.x] : 0;
    int total;
    int excl = block_excl_scan(v, warp_sums, &total);
    if (threadIdx.x < nblocks) g_bsum[threadIdx.x] = excl;
    if (threadIdx.x == 0) g_offset[N] = total;
}

__global__ __launch_bounds__(SCAN_CHUNK)
void scan_part3_kernel(int N)
{
    int i = blockIdx.x * SCAN_CHUNK + threadIdx.x;
    if (i < N) {
        int o = g_offset[i] + g_bsum[blockIdx.x];
        g_offset[i] = o;
        g_cursor[i] = o;
    }
}

__global__ void reorder_kernel(const int* __restrict__ rows,
                               const int* __restrict__ cols,
                               const float* __restrict__ vals,
                               int E)
{
    int i = blockIdx.x * blockDim.x + threadIdx.x;
    if (i >= E) return;
    int r = rows[i];
    int pos = atomicAdd(&g_cursor[r], 1);
    g_edges[pos] = make_int2(cols[i], __float_as_int(vals[i]));
}

// ===========================================================================
// Gather SpMM (unchanged)
// ===========================================================================
__device__ __forceinline__ void fma8_h(const uint4 p, float v, float* acc)
{
    float2 f0 = __half22float2(*(const __half2*)&p.x);
    float2 f1 = __half22float2(*(const __half2*)&p.y);
    float2 f2 = __half22float2(*(const __half2*)&p.z);
    float2 f3 = __half22float2(*(const __half2*)&p.w);
    acc[0] = fmaf(v, f0.x, acc[0]);
    acc[1] = fmaf(v, f0.y, acc[1]);
    acc[2] = fmaf(v, f1.x, acc[2]);
    acc[3] = fmaf(v, f1.y, acc[3]);
    acc[4] = fmaf(v, f2.x, acc[4]);
    acc[5] = fmaf(v, f2.y, acc[5]);
    acc[6] = fmaf(v, f3.x, acc[6]);
    acc[7] = fmaf(v, f3.y, acc[7]);
}

__global__ __launch_bounds__(256)
void gather_kernel(float* __restrict__ out, int N)
{
    int warp = (blockIdx.x * blockDim.x + threadIdx.x) >> 5;
    int lane = threadIdx.x & 31;
    if (warp >= N) return;

    int beg = g_offset[warp];
    int end = g_offset[warp + 1];

    float acc[8];
    #pragma unroll
    for (int j = 0; j < 8; j++) acc[j] = 0.0f;

    int e = beg;
    for (; e + 1 < end; e += 2) {
        int2 ed0 = g_edges[e];
        int2 ed1 = g_edges[e + 1];
        const uint4* s0 = (const uint4*)(g_support + (size_t)ed0.x * OUT_DIM);
        const uint4* s1 = (const uint4*)(g_support + (size_t)ed1.x * OUT_DIM);
        uint4 p0 = s0[lane];
        uint4 p1 = s1[lane];
        fma8_h(p0, __int_as_float(ed0.y), acc);
        fma8_h(p1, __int_as_float(ed1.y), acc);
    }
    if (e < end) {
        int2 ed = g_edges[e];
        const uint4* s = (const uint4*)(g_support + (size_t)ed.x * OUT_DIM);
        uint4 p = s[lane];
        fma8_h(p, __int_as_float(ed.y), acc);
    }

    float* dst = out + (size_t)warp * OUT_DIM + lane * 8;
    *(float4*)(dst)     = make_float4(acc[0], acc[1], acc[2], acc[3]);
    *(float4*)(dst + 4) = make_float4(acc[4], acc[5], acc[6], acc[7]);
}

// ===========================================================================
// Launch
// ===========================================================================
extern "C" void kernel_launch(void* const* d_in, const int* in_sizes, int n_in,
                              void* d_out, int out_size)
{
    const float* x      = (const float*)d_in[0];
    const float* w      = (const float*)d_in[1];
    const int*   erows  = (const int*)d_in[2];
    const int*   ecols  = (const int*)d_in[3];
    const float* evals  = (const float*)d_in[4];
    const int*   active = (const int*)d_in[5];
    float*       out    = (float*)d_out;

    const int N = in_sizes[0] / IN_DIM;
    const int E = in_sizes[2];
    const int nsb = (N + SCAN_CHUNK - 1) / SCAN_CHUNK;

    cudaFuncSetAttribute(gemm_hist_kernel,
                         cudaFuncAttributeMaxDynamicSharedMemorySize, GEMM_SMEM);

    // prelude: weight transpose+convert || zero counters
    int zero_blocks = (N + 255) / 256;
    prelude_kernel<<<TRANS_BLOCKS + zero_blocks, 256>>>(w, N);

    // fused GEMM (single-pass N) || histogram
    int gemm_blocks = (N + 63) / 64;
    gemm_hist_kernel<<<gemm_blocks + HIST_BLOCKS, 256, GEMM_SMEM>>>(
        x, active, erows, N, E, gemm_blocks);

    // scan
    scan_part1_kernel<<<nsb, SCAN_CHUNK>>>(N);
    scan_part2_kernel<<<1, 128>>>(nsb, N);
    scan_part3_kernel<<<nsb, SCAN_CHUNK>>>(N);

    // reorder into CSR order
    reorder_kernel<<<(E + 255) / 256, 256>>>(erows, ecols, evals, E);

    // gather SpMM
    int gblocks = (N * 32 + 255) / 256;
    gather_kernel<<<gblocks, 256>>>(out, N);
}

// round 10
// speedup vs baseline: 4.9503x; 1.0080x over previous
#include <cuda_runtime.h>
#include <cuda_fp16.h>
#include <cstdint>

// Problem constants: N=100000, IN=512, OUT=256, E=3.2M
#define IN_DIM  512
#define OUT_DIM 256
#define MAX_N   100000
#define MAX_E   3200000
#define SCAN_CHUNK 1024
#define SCAN_BLOCKS ((MAX_N + SCAN_CHUNK - 1) / SCAN_CHUNK)   // 98

// Scratch (device globals -- no runtime allocation allowed)
__device__ __half g_support[(size_t)MAX_N * OUT_DIM];  // 51.2 MB fp16
__device__ __half g_wh[(size_t)OUT_DIM * IN_DIM];      // w^T [256][512] fp16, K-major
__device__ int    g_count[MAX_N];
__device__ int    g_offset[MAX_N + 1];
__device__ int    g_cursor[MAX_N];
__device__ int    g_bsum[SCAN_BLOCKS + 1];
__device__ int2   g_edges[MAX_E];

// ===========================================================================
// PTX helpers
// ===========================================================================
__device__ __forceinline__ uint32_t smem_u32(const void* p) {
    uint32_t a;
    asm("{ .reg .u64 t; cvta.to.shared.u64 t, %1; cvt.u32.u64 %0, t; }"
        : "=r"(a) : "l"(p));
    return a;
}

__device__ __forceinline__ void cp_async16(uint32_t dst, const void* src) {
    asm volatile("cp.async.cg.shared.global [%0], [%1], 16;"
                 :: "r"(dst), "l"(src) : "memory");
}
#define CP_COMMIT() asm volatile("cp.async.commit_group;" ::: "memory")
#define CP_WAIT0()  asm volatile("cp.async.wait_group 0;" ::: "memory")

__device__ __forceinline__ void ldsm_x4(uint32_t* r, uint32_t addr) {
    asm volatile("ldmatrix.sync.aligned.m8n8.x4.shared.b16 {%0,%1,%2,%3}, [%4];"
                 : "=r"(r[0]), "=r"(r[1]), "=r"(r[2]), "=r"(r[3]) : "r"(addr));
}

__device__ __forceinline__ void mma16816(float* c, const uint32_t* a, const uint32_t* b) {
    asm volatile(
        "mma.sync.aligned.m16n8k16.row.col.f32.f16.f16.f32 "
        "{%0,%1,%2,%3}, {%4,%5,%6,%7}, {%8,%9}, {%0,%1,%2,%3};"
        : "+f"(c[0]), "+f"(c[1]), "+f"(c[2]), "+f"(c[3])
        : "r"(a[0]), "r"(a[1]), "r"(a[2]), "r"(a[3]), "r"(b[0]), "r"(b[1]));
}

// ===========================================================================
// Prelude: transpose+convert weight (blocks 0-127) || zero g_count (rest)
// ===========================================================================
#define TRANS_BLOCKS 128          // (OUT/32) * (IN/32) = 8*16

__global__ __launch_bounds__(256)
void prelude_kernel(const float* __restrict__ w, int N)
{
    __shared__ float tile[32][33];
    const int tid = threadIdx.x;
    if (blockIdx.x < TRANS_BLOCKS) {
        int n0 = (blockIdx.x & 7) * 32;
        int k0 = (blockIdx.x >> 3) * 32;
        int tx = tid & 31;
        int ty = tid >> 5;              // 0..7
        #pragma unroll
        for (int i = 0; i < 4; i++)
            tile[ty + 8 * i][tx] = w[(size_t)(k0 + ty + 8 * i) * OUT_DIM + n0 + tx];
        __syncthreads();
        #pragma unroll
        for (int i = 0; i < 4; i++)
            g_wh[(size_t)(n0 + ty + 8 * i) * IN_DIM + k0 + tx]
                = __float2half(tile[tx][ty + 8 * i]);
    } else {
        int i = (blockIdx.x - TRANS_BLOCKS) * 256 + tid;
        if (i < N) g_count[i] = 0;
    }
}

// ===========================================================================
// Histogram (standalone; runs right after prelude, before scan)
// ===========================================================================
__global__ void hist_kernel(const int* __restrict__ rows, int E)
{
    int i = blockIdx.x * blockDim.x + threadIdx.x;
    int base = i * 4;
    if (base + 3 < E) {
        int4 r = *(const int4*)(rows + base);
        atomicAdd(&g_count[r.x], 1);
        atomicAdd(&g_count[r.y], 1);
        atomicAdd(&g_count[r.z], 1);
        atomicAdd(&g_count[r.w], 1);
    } else {
        for (int j = base; j < E; j++) atomicAdd(&g_count[rows[j]], 1);
    }
}

// ===========================================================================
// Parallel scan (unchanged)
// ===========================================================================
__device__ __forceinline__ int block_excl_scan(int v, int* warp_sums, int* total)
{
    const int lane = threadIdx.x & 31;
    const int wid  = threadIdx.x >> 5;
    const int nw   = blockDim.x >> 5;

    int s = v;
    #pragma unroll
    for (int off = 1; off < 32; off <<= 1) {
        int t = __shfl_up_sync(0xFFFFFFFFu, s, off);
        if (lane >= off) s += t;
    }
    if (lane == 31) warp_sums[wid] = s;
    __syncthreads();
    if (wid == 0) {
        int ws = (lane < nw) ? warp_sums[lane] : 0;
        #pragma unroll
        for (int off = 1; off < 32; off <<= 1) {
            int t = __shfl_up_sync(0xFFFFFFFFu, ws, off);
            if (lane >= off) ws += t;
        }
        if (lane < nw) warp_sums[lane] = ws;
    }
    __syncthreads();
    *total = warp_sums[nw - 1];
    return (wid > 0 ? warp_sums[wid - 1] : 0) + (s - v);
}

__global__ __launch_bounds__(SCAN_CHUNK)
void scan_part1_kernel(int N)
{
    __shared__ int warp_sums[32];
    int i = blockIdx.x * SCAN_CHUNK + threadIdx.x;
    int v = (i < N) ? g_count[i] : 0;
    int total;
    int excl = block_excl_scan(v, warp_sums, &total);
    if (i < N) g_offset[i] = excl;
    if (threadIdx.x == 0) g_bsum[blockIdx.x] = total;
}

__global__ __launch_bounds__(128)
void scan_part2_kernel(int nblocks, int N)
{
    __shared__ int warp_sums[32];
    int v = (threadIdx.x < nblocks) ? g_bsum[threadIdx.x] : 0;
    int total;
    int excl = block_excl_scan(v, warp_sums, &total);
    if (threadIdx.x < nblocks) g_bsum[threadIdx.x] = excl;
    if (threadIdx.x == 0) g_offset[N] = total;
}

__global__ __launch_bounds__(SCAN_CHUNK)
void scan_part3_kernel(int N)
{
    int i = blockIdx.x * SCAN_CHUNK + threadIdx.x;
    if (i < N) {
        int o = g_offset[i] + g_bsum[blockIdx.x];
        g_offset[i] = o;
        g_cursor[i] = o;
    }
}

// ===========================================================================
// Fused: HMMA GEMM || reorder, interleaved 3:1 so reorder CTAs occupy every
// wave and hide under the GEMM. group g = bid>>2; sub = bid&3.
//   sub 0..2 -> gemm block g*3+sub;  sub 3 -> reorder block g.
// GEMM: CTA 64(M) x 256(N), single N pass, 8 warps x (32x64), BK=32.
// ===========================================================================
#define GSTRIDE 40                 // halves per SMEM row (32 data + 8 pad)
#define NSTAGE  16                 // 512 / 32
#define OFF_A0  0
#define OFF_A1  (64 * GSTRIDE * 2)                 // 5120
#define OFF_B0  (2 * 64 * GSTRIDE * 2)             // 10240
#define OFF_B1  (OFF_B0 + 256 * GSTRIDE * 2)       // 30720
#define GEMM_SMEM (OFF_B1 + 256 * GSTRIDE * 2)     // 51200

__global__ __launch_bounds__(256, 2)
void gemm_reorder_kernel(const float* __restrict__ x,
                         const int*   __restrict__ active,
                         const int*   __restrict__ rows,
                         const int*   __restrict__ cols,
                         const float* __restrict__ vals,
                         int N, int E, int ngroups)
{
    extern __shared__ char dsm[];
    const int tid = threadIdx.x;
    const int g   = blockIdx.x >> 2;
    const int sub = blockIdx.x & 3;

    if (sub == 3) {
        // ------------- reorder body (grid-stride over edges) ----------------
        const int span = ngroups * 256;
        for (int i = g * 256 + tid; i < E; i += span) {
            int r = rows[i];
            int pos = atomicAdd(&g_cursor[r], 1);
            g_edges[pos] = make_int2(cols[i], __float_as_int(vals[i]));
        }
        return;
    }

    const int gemm_bid = g * 3 + sub;
    const int block_row = gemm_bid * 64;
    if (block_row >= N) return;

    // -------------------------- GEMM body -----------------------------------
    const int wid  = tid >> 5;
    const int lane = tid & 31;

    const int mbase = (wid & 1) * 32;
    const int nbase = (wid >> 1) * 64;

    float acc[2][8][4];
    #pragma unroll
    for (int mt = 0; mt < 2; mt++)
        #pragma unroll
        for (int nt = 0; nt < 8; nt++)
            #pragma unroll
            for (int j = 0; j < 4; j++)
                acc[mt][nt][j] = 0.0f;

    const int a_r0 = tid >> 3;
    const int a_r1 = (tid + 256) >> 3;
    const int a_q  = tid & 7;
    int ag0 = block_row + a_r0; if (ag0 >= N) ag0 = N - 1;
    int ag1 = block_row + a_r1; if (ag1 >= N) ag1 = N - 1;
    const float* ap0 = x + (size_t)ag0 * IN_DIM + a_q * 4;
    const float* ap1 = x + (size_t)ag1 * IN_DIM + a_q * 4;

    int b_n[4], b_q[4];
    const __half* bp[4];
    #pragma unroll
    for (int i = 0; i < 4; i++) {
        int c = tid + 256 * i;
        b_n[i] = c >> 2;
        b_q[i] = c & 3;
        bp[i] = g_wh + (size_t)b_n[i] * IN_DIM + b_q[i] * 8;
    }

    const uint32_t aS[2] = { smem_u32(dsm + OFF_A0), smem_u32(dsm + OFF_A1) };
    const uint32_t bS[2] = { smem_u32(dsm + OFF_B0), smem_u32(dsm + OFF_B1) };

    auto load_B = [&](int s, int buf) {
        const int k0 = s * 32;
        #pragma unroll
        for (int i = 0; i < 4; i++)
            cp_async16(bS[buf] + (b_n[i] * GSTRIDE + b_q[i] * 8) * 2, bp[i] + k0);
        CP_COMMIT();
    };

    auto store_A = [&](int buf, const float4 av0, const float4 av1) {
        __half* dA = (__half*)(dsm + (buf ? OFF_A1 : OFF_A0));
        __half* d0 = dA + a_r0 * GSTRIDE + a_q * 4;
        __half* d1 = dA + a_r1 * GSTRIDE + a_q * 4;
        *(__half2*)(d0)     = __float22half2_rn(make_float2(av0.x, av0.y));
        *(__half2*)(d0 + 2) = __float22half2_rn(make_float2(av0.z, av0.w));
        *(__half2*)(d1)     = __float22half2_rn(make_float2(av1.x, av1.y));
        *(__half2*)(d1 + 2) = __float22half2_rn(make_float2(av1.z, av1.w));
    };

    {
        load_B(0, 0);
        float4 av0 = *(const float4*)(ap0);
        float4 av1 = *(const float4*)(ap1);
        store_A(0, av0, av1);
        CP_WAIT0();
        __syncthreads();
    }

    int buf = 0;
    for (int s = 0; s < NSTAGE; s++) {
        float4 av0, av1;
        if (s < NSTAGE - 1) {
            const int k0n = (s + 1) * 32;
            av0 = *(const float4*)(ap0 + k0n);
            av1 = *(const float4*)(ap1 + k0n);
            load_B(s + 1, buf ^ 1);
        }

        const int ar   = lane & 7;
        const int amid = (lane >> 3) & 1;
        const int akh  = lane >> 4;
        #pragma unroll
        for (int ks = 0; ks < 2; ks++) {
            uint32_t afrag[2][4];
            #pragma unroll
            for (int mt = 0; mt < 2; mt++) {
                uint32_t addr = aS[buf] +
                    ((mbase + mt * 16 + amid * 8 + ar) * GSTRIDE + ks * 16 + akh * 8) * 2;
                ldsm_x4(afrag[mt], addr);
            }
            #pragma unroll
            for (int np = 0; np < 4; np++) {
                uint32_t bfrag[4];
                uint32_t baddr = bS[buf] +
                    ((nbase + np * 16 + (lane >> 4) * 8 + (lane & 7)) * GSTRIDE
                     + ks * 16 + ((lane >> 3) & 1) * 8) * 2;
                ldsm_x4(bfrag, baddr);
                #pragma unroll
                for (int mt = 0; mt < 2; mt++) {
                    mma16816(acc[mt][np * 2],     afrag[mt], &bfrag[0]);
                    mma16816(acc[mt][np * 2 + 1], afrag[mt], &bfrag[2]);
                }
            }
        }

        if (s < NSTAGE - 1) {
            store_A(buf ^ 1, av0, av1);
            CP_WAIT0();
            __syncthreads();
            buf ^= 1;
        }
    }

    const bool act = (*active) != 0;
    #pragma unroll
    for (int mt = 0; mt < 2; mt++) {
        const int gm0 = block_row + mbase + mt * 16 + (lane >> 2);
        const int gm1 = gm0 + 8;
        #pragma unroll
        for (int nt = 0; nt < 8; nt++) {
            const int gn = nbase + nt * 8 + (lane & 3) * 2;
            float c0 = acc[mt][nt][0], c1 = acc[mt][nt][1];
            float c2 = acc[mt][nt][2], c3 = acc[mt][nt][3];
            if (act) { c0 = tanhf(c0); c1 = tanhf(c1); c2 = tanhf(c2); c3 = tanhf(c3); }
            if (gm0 < N)
                *(__half2*)&g_support[(size_t)gm0 * OUT_DIM + gn]
                    = __float22half2_rn(make_float2(c0, c1));
            if (gm1 < N)
                *(__half2*)&g_support[(size_t)gm1 * OUT_DIM + gn]
                    = __float22half2_rn(make_float2(c2, c3));
        }
    }
}

// ===========================================================================
// Gather SpMM (unchanged)
// ===========================================================================
__device__ __forceinline__ void fma8_h(const uint4 p, float v, float* acc)
{
    float2 f0 = __half22float2(*(const __half2*)&p.x);
    float2 f1 = __half22float2(*(const __half2*)&p.y);
    float2 f2 = __half22float2(*(const __half2*)&p.z);
    float2 f3 = __half22float2(*(const __half2*)&p.w);
    acc[0] = fmaf(v, f0.x, acc[0]);
    acc[1] = fmaf(v, f0.y, acc[1]);
    acc[2] = fmaf(v, f1.x, acc[2]);
    acc[3] = fmaf(v, f1.y, acc[3]);
    acc[4] = fmaf(v, f2.x, acc[4]);
    acc[5] = fmaf(v, f2.y, acc[5]);
    acc[6] = fmaf(v, f3.x, acc[6]);
    acc[7] = fmaf(v, f3.y, acc[7]);
}

__global__ __launch_bounds__(256)
void gather_kernel(float* __restrict__ out, int N)
{
    int warp = (blockIdx.x * blockDim.x + threadIdx.x) >> 5;
    int lane = threadIdx.x & 31;
    if (warp >= N) return;

    int beg = g_offset[warp];
    int end = g_offset[warp + 1];

    float acc[8];
    #pragma unroll
    for (int j = 0; j < 8; j++) acc[j] = 0.0f;

    int e = beg;
    for (; e + 1 < end; e += 2) {
        int2 ed0 = g_edges[e];
        int2 ed1 = g_edges[e + 1];
        const uint4* s0 = (const uint4*)(g_support + (size_t)ed0.x * OUT_DIM);
        const uint4* s1 = (const uint4*)(g_support + (size_t)ed1.x * OUT_DIM);
        uint4 p0 = s0[lane];
        uint4 p1 = s1[lane];
        fma8_h(p0, __int_as_float(ed0.y), acc);
        fma8_h(p1, __int_as_float(ed1.y), acc);
    }
    if (e < end) {
        int2 ed = g_edges[e];
        const uint4* s = (const uint4*)(g_support + (size_t)ed.x * OUT_DIM);
        uint4 p = s[lane];
        fma8_h(p, __int_as_float(ed.y), acc);
    }

    float* dst = out + (size_t)warp * OUT_DIM + lane * 8;
    *(float4*)(dst)     = make_float4(acc[0], acc[1], acc[2], acc[3]);
    *(float4*)(dst + 4) = make_float4(acc[4], acc[5], acc[6], acc[7]);
}

// ===========================================================================
// Launch
// ===========================================================================
extern "C" void kernel_launch(void* const* d_in, const int* in_sizes, int n_in,
                              void* d_out, int out_size)
{
    const float* x      = (const float*)d_in[0];
    const float* w      = (const float*)d_in[1];
    const int*   erows  = (const int*)d_in[2];
    const int*   ecols  = (const int*)d_in[3];
    const float* evals  = (const float*)d_in[4];
    const int*   active = (const int*)d_in[5];
    float*       out    = (float*)d_out;

    const int N = in_sizes[0] / IN_DIM;
    const int E = in_sizes[2];
    const int nsb = (N + SCAN_CHUNK - 1) / SCAN_CHUNK;

    cudaFuncSetAttribute(gemm_reorder_kernel,
                         cudaFuncAttributeMaxDynamicSharedMemorySize, GEMM_SMEM);

    // prelude: weight transpose+convert || zero counters
    int zero_blocks = (N + 255) / 256;
    prelude_kernel<<<TRANS_BLOCKS + zero_blocks, 256>>>(w, N);

    // histogram (standalone, fast)
    hist_kernel<<<((E + 3) / 4 + 255) / 256, 256>>>(erows, E);

    // scan -> offsets + cursors
    scan_part1_kernel<<<nsb, SCAN_CHUNK>>>(N);
    scan_part2_kernel<<<1, 128>>>(nsb, N);
    scan_part3_kernel<<<nsb, SCAN_CHUNK>>>(N);

    // fused GEMM || reorder (3:1 interleaved)
    int gemm_blocks = (N + 63) / 64;            // 1563
    int ngroups = (gemm_blocks + 2) / 3;        // 521
    gemm_reorder_kernel<<<ngroups * 4, 256, GEMM_SMEM>>>(
        x, active, erows, ecols, evals, N, E, ngroups);

    // gather SpMM
    int gblocks = (N * 32 + 255) / 256;
    gather_kernel<<<gblocks, 256>>>(out, N);
}

// round 13
// speedup vs baseline: 4.9992x; 1.0099x over previous
#include <cuda_runtime.h>
#include <cuda_fp16.h>
#include <cstdint>

// Problem constants: N=100000, IN=512, OUT=256, E=3.2M
#define IN_DIM  512
#define OUT_DIM 256
#define MAX_N   100000
#define MAX_E   3200000
#define SCAN_CHUNK 1024
#define SCAN_BLOCKS ((MAX_N + SCAN_CHUNK - 1) / SCAN_CHUNK)   // 98

// Scratch (device globals; g_count relies on static zero-init + re-zero in scan_part3)
__device__ __half g_support[(size_t)MAX_N * OUT_DIM];  // 51.2 MB fp16
__device__ __half g_wh[(size_t)OUT_DIM * IN_DIM];      // w^T [256][512] fp16, K-major
__device__ int    g_count[MAX_N];                      // ALWAYS zero between runs
__device__ int    g_offset[MAX_N + 1];
__device__ int    g_cursor[MAX_N];
__device__ int    g_bsum[SCAN_BLOCKS + 1];
__device__ int2   g_edges[MAX_E];

// ===========================================================================
// PTX helpers
// ===========================================================================
__device__ __forceinline__ uint32_t smem_u32(const void* p) {
    uint32_t a;
    asm("{ .reg .u64 t; cvta.to.shared.u64 t, %1; cvt.u32.u64 %0, t; }"
        : "=r"(a) : "l"(p));
    return a;
}

__device__ __forceinline__ void cp_async16(uint32_t dst, const void* src) {
    asm volatile("cp.async.cg.shared.global [%0], [%1], 16;"
                 :: "r"(dst), "l"(src) : "memory");
}
#define CP_COMMIT() asm volatile("cp.async.commit_group;" ::: "memory")
#define CP_WAIT0()  asm volatile("cp.async.wait_group 0;" ::: "memory")

__device__ __forceinline__ void ldsm_x4(uint32_t* r, uint32_t addr) {
    asm volatile("ldmatrix.sync.aligned.m8n8.x4.shared.b16 {%0,%1,%2,%3}, [%4];"
                 : "=r"(r[0]), "=r"(r[1]), "=r"(r[2]), "=r"(r[3]) : "r"(addr));
}

__device__ __forceinline__ void mma16816(float* c, const uint32_t* a, const uint32_t* b) {
    asm volatile(
        "mma.sync.aligned.m16n8k16.row.col.f32.f16.f16.f32 "
        "{%0,%1,%2,%3}, {%4,%5,%6,%7}, {%8,%9}, {%0,%1,%2,%3};"
        : "+f"(c[0]), "+f"(c[1]), "+f"(c[2]), "+f"(c[3])
        : "r"(a[0]), "r"(a[1]), "r"(a[2]), "r"(a[3]), "r"(b[0]), "r"(b[1]));
}

// ===========================================================================
// Prelude: weight transpose+convert (blocks 0-127) || histogram (rest).
// Independent tasks: transpose feeds GEMM; hist feeds scan. g_count arrives
// zeroed (static init on run 1; scan_part3 re-zeroes it every run).
// ===========================================================================
#define TRANS_BLOCKS 128          // (OUT/32) * (IN/32) = 8*16
#define HIST_BLOCKS  2048

__global__ __launch_bounds__(256)
void prelude_kernel(const float* __restrict__ w, const int* __restrict__ rows,
                    int E)
{
    __shared__ float tile[32][33];
    const int tid = threadIdx.x;
    if (blockIdx.x < TRANS_BLOCKS) {
        int n0 = (blockIdx.x & 7) * 32;
        int k0 = (blockIdx.x >> 3) * 32;
        int tx = tid & 31;
        int ty = tid >> 5;              // 0..7
        #pragma unroll
        for (int i = 0; i < 4; i++)
            tile[ty + 8 * i][tx] = w[(size_t)(k0 + ty + 8 * i) * OUT_DIM + n0 + tx];
        __syncthreads();
        #pragma unroll
        for (int i = 0; i < 4; i++)
            g_wh[(size_t)(n0 + ty + 8 * i) * IN_DIM + k0 + tx]
                = __float2half(tile[tx][ty + 8 * i]);
    } else {
        const int qid  = (blockIdx.x - TRANS_BLOCKS) * 256 + tid;
        const int span = HIST_BLOCKS * 256;
        const int nquads = E >> 2;
        for (int q = qid; q < nquads; q += span) {
            int4 r = *(const int4*)(rows + q * 4);
            atomicAdd(&g_count[r.x], 1);
            atomicAdd(&g_count[r.y], 1);
            atomicAdd(&g_count[r.z], 1);
            atomicAdd(&g_count[r.w], 1);
        }
        if (qid == 0)
            for (int j = nquads * 4; j < E; j++) atomicAdd(&g_count[rows[j]], 1);
    }
}

// ===========================================================================
// Parallel scan; part3 also RE-ZEROES g_count (free zeroing for next run)
// ===========================================================================
__device__ __forceinline__ int block_excl_scan(int v, int* warp_sums, int* total)
{
    const int lane = threadIdx.x & 31;
    const int wid  = threadIdx.x >> 5;
    const int nw   = blockDim.x >> 5;

    int s = v;
    #pragma unroll
    for (int off = 1; off < 32; off <<= 1) {
        int t = __shfl_up_sync(0xFFFFFFFFu, s, off);
        if (lane >= off) s += t;
    }
    if (lane == 31) warp_sums[wid] = s;
    __syncthreads();
    if (wid == 0) {
        int ws = (lane < nw) ? warp_sums[lane] : 0;
        #pragma unroll
        for (int off = 1; off < 32; off <<= 1) {
            int t = __shfl_up_sync(0xFFFFFFFFu, ws, off);
            if (lane >= off) ws += t;
        }
        if (lane < nw) warp_sums[lane] = ws;
    }
    __syncthreads();
    *total = warp_sums[nw - 1];
    return (wid > 0 ? warp_sums[wid - 1] : 0) + (s - v);
}

__global__ __launch_bounds__(SCAN_CHUNK)
void scan_part1_kernel(int N)
{
    __shared__ int warp_sums[32];
    int i = blockIdx.x * SCAN_CHUNK + threadIdx.x;
    int v = (i < N) ? g_count[i] : 0;
    int total;
    int excl = block_excl_scan(v, warp_sums, &total);
    if (i < N) g_offset[i] = excl;
    if (threadIdx.x == 0) g_bsum[blockIdx.x] = total;
}

__global__ __launch_bounds__(128)
void scan_part2_kernel(int nblocks, int N)
{
    __shared__ int warp_sums[32];
    int v = (threadIdx.x < nblocks) ? g_bsum[threadIdx.x] : 0;
    int total;
    int excl = block_excl_scan(v, warp_sums, &total);
    if (threadIdx.x < nblocks) g_bsum[threadIdx.x] = excl;
    if (threadIdx.x == 0) g_offset[N] = total;
}

__global__ __launch_bounds__(SCAN_CHUNK)
void scan_part3_kernel(int N)
{
    int i = blockIdx.x * SCAN_CHUNK + threadIdx.x;
    if (i < N) {
        int o = g_offset[i] + g_bsum[blockIdx.x];
        g_offset[i] = o;
        g_cursor[i] = o;
        g_count[i]  = 0;          // free re-zero for the next invocation
    }
}

// ===========================================================================
// Fused: HMMA GEMM || reorder (3:1 interleave).
// GEMM: CTA tile 128(M) x 256(N), 512 threads, 16 warps x (32x64), BK=32,
// double-buffered. Halves per-row B L2 traffic vs BM=64.
// ===========================================================================
#define GSTRIDE 40                 // halves per SMEM row (32 data + 8 pad)
#define NSTAGE  16                 // 512 / 32
#define OFF_A0  0
#define OFF_A1  (128 * GSTRIDE * 2)                // 10240
#define OFF_B0  (2 * 128 * GSTRIDE * 2)            // 20480
#define OFF_B1  (OFF_B0 + 256 * GSTRIDE * 2)       // 40960
#define GEMM_SMEM (OFF_B1 + 256 * GSTRIDE * 2)     // 61440

__global__ __launch_bounds__(512, 1)
void gemm_reorder_kernel(const float* __restrict__ x,
                         const int*   __restrict__ active,
                         const int*   __restrict__ rows,
                         const int*   __restrict__ cols,
                         const float* __restrict__ vals,
                         int N, int E, int ngroups)
{
    extern __shared__ char dsm[];
    const int tid = threadIdx.x;
    const int g   = blockIdx.x >> 2;
    const int sub = blockIdx.x & 3;

    if (sub == 3) {
        // ------------- reorder body (grid-stride over edges) ----------------
        const int span = ngroups * 512;
        for (int i = g * 512 + tid; i < E; i += span) {
            int r = rows[i];
            int pos = atomicAdd(&g_cursor[r], 1);
            g_edges[pos] = make_int2(cols[i], __float_as_int(vals[i]));
        }
        return;
    }

    const int gemm_bid = g * 3 + sub;
    const int block_row = gemm_bid * 128;
    if (block_row >= N) return;

    // -------------------------- GEMM body -----------------------------------
    const int wid  = tid >> 5;
    const int lane = tid & 31;

    const int mbase = (wid & 3) * 32;      // 4 M bands
    const int nbase = (wid >> 2) * 64;     // 4 N bands

    float acc[2][8][4];
    #pragma unroll
    for (int mt = 0; mt < 2; mt++)
        #pragma unroll
        for (int nt = 0; nt < 8; nt++)
            #pragma unroll
            for (int j = 0; j < 4; j++)
                acc[mt][nt][j] = 0.0f;

    // A: 128 rows x 32 f32/stage = 1024 float4 chunks; 2 per thread
    const int a_r0 = tid >> 3;             // 0..63
    const int a_r1 = (tid + 512) >> 3;     // 64..127
    const int a_q  = tid & 7;
    int ag0 = block_row + a_r0; if (ag0 >= N) ag0 = N - 1;
    int ag1 = block_row + a_r1; if (ag1 >= N) ag1 = N - 1;
    const float* ap0 = x + (size_t)ag0 * IN_DIM + a_q * 4;
    const float* ap1 = x + (size_t)ag1 * IN_DIM + a_q * 4;

    // B: 256 rows x 32 halves/stage = 1024 16B chunks; 2 per thread
    int b_n[2], b_q[2];
    const __half* bp[2];
    #pragma unroll
    for (int i = 0; i < 2; i++) {
        int c = tid + 512 * i;
        b_n[i] = c >> 2;
        b_q[i] = c & 3;
        bp[i] = g_wh + (size_t)b_n[i] * IN_DIM + b_q[i] * 8;
    }

    const uint32_t aS[2] = { smem_u32(dsm + OFF_A0), smem_u32(dsm + OFF_A1) };
    const uint32_t bS[2] = { smem_u32(dsm + OFF_B0), smem_u32(dsm + OFF_B1) };

    auto load_B = [&](int s, int buf) {
        const int k0 = s * 32;
        #pragma unroll
        for (int i = 0; i < 2; i++)
            cp_async16(bS[buf] + (b_n[i] * GSTRIDE + b_q[i] * 8) * 2, bp[i] + k0);
        CP_COMMIT();
    };

    auto store_A = [&](int buf, const float4 av0, const float4 av1) {
        __half* dA = (__half*)(dsm + (buf ? OFF_A1 : OFF_A0));
        __half* d0 = dA + a_r0 * GSTRIDE + a_q * 4;
        __half* d1 = dA + a_r1 * GSTRIDE + a_q * 4;
        *(__half2*)(d0)     = __float22half2_rn(make_float2(av0.x, av0.y));
        *(__half2*)(d0 + 2) = __float22half2_rn(make_float2(av0.z, av0.w));
        *(__half2*)(d1)     = __float22half2_rn(make_float2(av1.x, av1.y));
        *(__half2*)(d1 + 2) = __float22half2_rn(make_float2(av1.z, av1.w));
    };

    {
        load_B(0, 0);
        float4 av0 = *(const float4*)(ap0);
        float4 av1 = *(const float4*)(ap1);
        store_A(0, av0, av1);
        CP_WAIT0();
        __syncthreads();
    }

    int buf = 0;
    for (int s = 0; s < NSTAGE; s++) {
        float4 av0, av1;
        if (s < NSTAGE - 1) {
            const int k0n = (s + 1) * 32;
            av0 = *(const float4*)(ap0 + k0n);
            av1 = *(const float4*)(ap1 + k0n);
            load_B(s + 1, buf ^ 1);
        }

        const int ar   = lane & 7;
        const int amid = (lane >> 3) & 1;
        const int akh  = lane >> 4;
        #pragma unroll
        for (int ks = 0; ks < 2; ks++) {
            uint32_t afrag[2][4];
            #pragma unroll
            for (int mt = 0; mt < 2; mt++) {
                uint32_t addr = aS[buf] +
                    ((mbase + mt * 16 + amid * 8 + ar) * GSTRIDE + ks * 16 + akh * 8) * 2;
                ldsm_x4(afrag[mt], addr);
            }
            #pragma unroll
            for (int np = 0; np < 4; np++) {
                uint32_t bfrag[4];
                uint32_t baddr = bS[buf] +
                    ((nbase + np * 16 + (lane >> 4) * 8 + (lane & 7)) * GSTRIDE
                     + ks * 16 + ((lane >> 3) & 1) * 8) * 2;
                ldsm_x4(bfrag, baddr);
                #pragma unroll
                for (int mt = 0; mt < 2; mt++) {
                    mma16816(acc[mt][np * 2],     afrag[mt], &bfrag[0]);
                    mma16816(acc[mt][np * 2 + 1], afrag[mt], &bfrag[2]);
                }
            }
        }

        if (s < NSTAGE - 1) {
            store_A(buf ^ 1, av0, av1);
            CP_WAIT0();
            __syncthreads();
            buf ^= 1;
        }
    }

    const bool act = (*active) != 0;
    #pragma unroll
    for (int mt = 0; mt < 2; mt++) {
        const int gm0 = block_row + mbase + mt * 16 + (lane >> 2);
        const int gm1 = gm0 + 8;
        #pragma unroll
        for (int nt = 0; nt < 8; nt++) {
            const int gn = nbase + nt * 8 + (lane & 3) * 2;
            float c0 = acc[mt][nt][0], c1 = acc[mt][nt][1];
            float c2 = acc[mt][nt][2], c3 = acc[mt][nt][3];
            if (act) { c0 = tanhf(c0); c1 = tanhf(c1); c2 = tanhf(c2); c3 = tanhf(c3); }
            if (gm0 < N)
                *(__half2*)&g_support[(size_t)gm0 * OUT_DIM + gn]
                    = __float22half2_rn(make_float2(c0, c1));
            if (gm1 < N)
                *(__half2*)&g_support[(size_t)gm1 * OUT_DIM + gn]
                    = __float22half2_rn(make_float2(c2, c3));
        }
    }
}

// ===========================================================================
// Gather SpMM (unchanged)
// ===========================================================================
__device__ __forceinline__ void fma8_h(const uint4 p, float v, float* acc)
{
    float2 f0 = __half22float2(*(const __half2*)&p.x);
    float2 f1 = __half22float2(*(const __half2*)&p.y);
    float2 f2 = __half22float2(*(const __half2*)&p.z);
    float2 f3 = __half22float2(*(const __half2*)&p.w);
    acc[0] = fmaf(v, f0.x, acc[0]);
    acc[1] = fmaf(v, f0.y, acc[1]);
    acc[2] = fmaf(v, f1.x, acc[2]);
    acc[3] = fmaf(v, f1.y, acc[3]);
    acc[4] = fmaf(v, f2.x, acc[4]);
    acc[5] = fmaf(v, f2.y, acc[5]);
    acc[6] = fmaf(v, f3.x, acc[6]);
    acc[7] = fmaf(v, f3.y, acc[7]);
}

__global__ __launch_bounds__(256)
void gather_kernel(float* __restrict__ out, int N)
{
    int warp = (blockIdx.x * blockDim.x + threadIdx.x) >> 5;
    int lane = threadIdx.x & 31;
    if (warp >= N) return;

    int beg = g_offset[warp];
    int end = g_offset[warp + 1];

    float acc[8];
    #pragma unroll
    for (int j = 0; j < 8; j++) acc[j] = 0.0f;

    int e = beg;
    for (; e + 1 < end; e += 2) {
        int2 ed0 = g_edges[e];
        int2 ed1 = g_edges[e + 1];
        const uint4* s0 = (const uint4*)(g_support + (size_t)ed0.x * OUT_DIM);
        const uint4* s1 = (const uint4*)(g_support + (size_t)ed1.x * OUT_DIM);
        uint4 p0 = s0[lane];
        uint4 p1 = s1[lane];
        fma8_h(p0, __int_as_float(ed0.y), acc);
        fma8_h(p1, __int_as_float(ed1.y), acc);
    }
    if (e < end) {
        int2 ed = g_edges[e];
        const uint4* s = (const uint4*)(g_support + (size_t)ed.x * OUT_DIM);
        uint4 p = s[lane];
        fma8_h(p, __int_as_float(ed.y), acc);
    }

    float* dst = out + (size_t)warp * OUT_DIM + lane * 8;
    *(float4*)(dst)     = make_float4(acc[0], acc[1], acc[2], acc[3]);
    *(float4*)(dst + 4) = make_float4(acc[4], acc[5], acc[6], acc[7]);
}

// ===========================================================================
// Launch
// ===========================================================================
extern "C" void kernel_launch(void* const* d_in, const int* in_sizes, int n_in,
                              void* d_out, int out_size)
{
    const float* x      = (const float*)d_in[0];
    const float* w      = (const float*)d_in[1];
    const int*   erows  = (const int*)d_in[2];
    const int*   ecols  = (const int*)d_in[3];
    const float* evals  = (const float*)d_in[4];
    const int*   active = (const int*)d_in[5];
    float*       out    = (float*)d_out;

    const int N = in_sizes[0] / IN_DIM;
    const int E = in_sizes[2];
    const int nsb = (N + SCAN_CHUNK - 1) / SCAN_CHUNK;

    cudaFuncSetAttribute(gemm_reorder_kernel,
                         cudaFuncAttributeMaxDynamicSharedMemorySize, GEMM_SMEM);

    // prelude: weight transpose+convert || histogram (g_count pre-zeroed)
    prelude_kernel<<<TRANS_BLOCKS + HIST_BLOCKS, 256>>>(w, erows, E);

    // scan -> offsets + cursors (part3 re-zeroes g_count)
    scan_part1_kernel<<<nsb, SCAN_CHUNK>>>(N);
    scan_part2_kernel<<<1, 128>>>(nsb, N);
    scan_part3_kernel<<<nsb, SCAN_CHUNK>>>(N);

    // fused GEMM (BM=128, single N pass) || reorder (3:1 interleaved)
    int gemm_blocks = (N + 127) / 128;          // 782
    int ngroups = (gemm_blocks + 2) / 3;        // 261
    gemm_reorder_kernel<<<ngroups * 4, 512, GEMM_SMEM>>>(
        x, active, erows, ecols, evals, N, E, ngroups);

    // gather SpMM
    int gblocks = (N * 32 + 255) / 256;
    gather_kernel<<<gblocks, 256>>>(out, N);
}